// round 7
// baseline (speedup 1.0000x reference)
#include <cuda_runtime.h>
#include <math.h>

#define FULLMASK 0xffffffffu

#define Bc 8
#define Tc 24
#define Nc 1000
#define Ec 1000
#define F_INc 16
#define C_RAWc 8
#define DMc 32
#define HCc 32
#define PREDc 12
#define LAMc 0.3f
#define EPSc 1e-8f
#define MAXD 64
#define ESTRIDE 24     // padded edge member list stride (int4-aligned)

typedef unsigned long long u64;

// ---------------- scratch (device globals; no allocation) ----------------
__device__ int   g_edge_nodes[Ec * ESTRIDE];
__device__ int   g_edge_cnt[Ec];
__device__ int   g_node_edges[Nc * MAXD];
__device__ int   g_node_deg[Nc];
__device__ float g_feat[Bc * Nc * 16];
__device__ float g_msum[Bc * Ec];
__device__ float g_Wd[Bc * Ec];
__device__ float g_dvi[Bc * Nc];
__device__ float g_ipwc[F_INc * DMc];   // folded ipw @ cw
__device__ float g_ipbc[DMc];           // folded ipb @ cw
__device__ float g_hc[(size_t)Bc * Nc * Tc * HCc];   // conv outputs (LSTM inputs)

// ---------------- math helpers ----------------
__device__ __forceinline__ float sigmf(float x) { return __fdividef(1.f, 1.f + __expf(-x)); }
__device__ __forceinline__ float tanhf_(float x) { return 2.f * sigmf(2.f * x) - 1.f; }
__device__ __forceinline__ float siluf(float x) { return x * sigmf(x); }

__device__ __forceinline__ u64 pack11(float x) {
    u64 r; asm("mov.b64 %0, {%1, %1};" : "=l"(r) : "f"(x)); return r;
}
__device__ __forceinline__ u64 packab(float a, float b) {
    u64 r; asm("mov.b64 %0, {%1, %2};" : "=l"(r) : "f"(a), "f"(b)); return r;
}
__device__ __forceinline__ void ffma2(u64& d, u64 a, u64 b) {
    asm("fma.rn.f32x2 %0, %1, %2, %0;" : "+l"(d) : "l"(a), "l"(b));
}
__device__ __forceinline__ float2 unpk(u64 v) {
    float2 f; asm("mov.b64 {%0, %1}, %2;" : "=f"(f.x), "=f"(f.y) : "l"(v)); return f;
}

// ---------------- adjacency build: zero + build + sort in one block ----------------
__global__ __launch_bounds__(1024) void k_adj(const int* __restrict__ members,
                                              const int* __restrict__ centers,
                                              const int* __restrict__ offsets) {
    int tid = threadIdx.x;
    if (tid < Nc) g_node_deg[tid] = 0;
    __syncthreads();

    if (tid < Ec) {
        int e = tid;
        int s = offsets[e], t = offsets[e + 1];
        int list[ESTRIDE];
        int cnt = 0;
        for (int m = s; m < t && cnt < ESTRIDE; m++) {
            int n = members[m];
            bool dup = false;
            for (int k = 0; k < cnt; k++) if (list[k] == n) { dup = true; break; }
            if (!dup) list[cnt++] = n;
        }
        {
            int c = centers[e];
            bool dup = false;
            for (int k = 0; k < cnt; k++) if (list[k] == c) { dup = true; break; }
            if (!dup && cnt < ESTRIDE) list[cnt++] = c;
        }
        g_edge_cnt[e] = cnt;
        for (int k = 0; k < cnt; k++) {
            int n = list[k];
            g_edge_nodes[e * ESTRIDE + k] = n;
            int pos = atomicAdd(&g_node_deg[n], 1);
            if (pos < MAXD) g_node_edges[n * MAXD + pos] = e;
        }
        for (int k = cnt; k < ESTRIDE; k++) g_edge_nodes[e * ESTRIDE + k] = Nc;
    }
    __syncthreads();

    if (tid < Nc) {
        int n = tid;
        int d = g_node_deg[n];
        if (d > MAXD) d = MAXD;
        g_node_deg[n] = d;
        int* L = g_node_edges + n * MAXD;
        for (int i = 1; i < d; i++) {
            int key = L[i];
            int j = i - 1;
            while (j >= 0 && L[j] > key) { L[j + 1] = L[j]; j--; }
            L[j + 1] = key;
        }
        int d8 = (d + 7) & ~7;
        if (d8 > MAXD) d8 = MAXD;
        for (int i = d; i < d8; i++) L[i] = Ec;  // dummy: smem row 1000 zeroed
    }
}

// ---------------- dynamic features: mean/std over T ----------------
__global__ void k_feat(const float* __restrict__ xraw) {
    int idx = blockIdx.x * blockDim.x + threadIdx.x;
    if (idx >= Bc * Nc * C_RAWc) return;
    int c = idx % C_RAWc;
    int n = (idx / C_RAWc) % Nc;
    int b = idx / (C_RAWc * Nc);
    float s1 = 0.f, s2 = 0.f;
    #pragma unroll
    for (int t = 0; t < Tc; t++) {
        float v = xraw[((b * Tc + t) * Nc + n) * C_RAWc + c];
        s1 += v; s2 += v * v;
    }
    float mean = s1 * (1.f / Tc);
    float var = s2 * (1.f / Tc) - mean * mean;
    if (var < 0.f) var = 0.f;
    g_feat[(b * Nc + n) * 16 + c] = mean;
    g_feat[(b * Nc + n) * 16 + C_RAWc + c] = sqrtf(var);
}

// ---------------- per-edge mean similarity (warp per (b,e)) ----------------
__global__ void k_sim(const int* __restrict__ members,
                      const int* __restrict__ centers,
                      const int* __restrict__ offsets) {
    int gid = blockIdx.x * (blockDim.x >> 5) + (threadIdx.x >> 5);
    if (gid >= Bc * Ec) return;
    int e = gid % Ec;
    int b = gid / Ec;
    int lane = threadIdx.x & 31;
    int s = offsets[e];
    int cntm = offsets[e + 1] - s;
    int cn = centers[e];
    const float4* cf4 = (const float4*)(g_feat + (b * Nc + cn) * 16);
    float4 c0 = cf4[0], c1 = cf4[1], c2 = cf4[2], c3 = cf4[3];
    float cn2 = c0.x*c0.x + c0.y*c0.y + c0.z*c0.z + c0.w*c0.w
              + c1.x*c1.x + c1.y*c1.y + c1.z*c1.z + c1.w*c1.w
              + c2.x*c2.x + c2.y*c2.y + c2.z*c2.z + c2.w*c2.w
              + c3.x*c3.x + c3.y*c3.y + c3.z*c3.z + c3.w*c3.w;
    float cnorm = sqrtf(cn2);
    float acc = 0.f;
    for (int m = lane; m < cntm; m += 32) {
        int n = members[s + m];
        const float4* mf4 = (const float4*)(g_feat + (b * Nc + n) * 16);
        float4 m0 = mf4[0], m1 = mf4[1], m2 = mf4[2], m3 = mf4[3];
        float dot = m0.x*c0.x + m0.y*c0.y + m0.z*c0.z + m0.w*c0.w
                  + m1.x*c1.x + m1.y*c1.y + m1.z*c1.z + m1.w*c1.w
                  + m2.x*c2.x + m2.y*c2.y + m2.z*c2.z + m2.w*c2.w
                  + m3.x*c3.x + m3.y*c3.y + m3.z*c3.z + m3.w*c3.w;
        float mn2 = m0.x*m0.x + m0.y*m0.y + m0.z*m0.z + m0.w*m0.w
                  + m1.x*m1.x + m1.y*m1.y + m1.z*m1.z + m1.w*m1.w
                  + m2.x*m2.x + m2.y*m2.y + m2.z*m2.z + m2.w*m2.w
                  + m3.x*m3.x + m3.y*m3.y + m3.z*m3.z + m3.w*m3.w;
        float sim = dot / (sqrtf(mn2) * cnorm + EPSc);
        acc += fminf(fmaxf(sim, 0.f), 1.f);
    }
    #pragma unroll
    for (int o = 16; o > 0; o >>= 1) acc += __shfl_xor_sync(FULLMASK, acc, o);
    if (lane == 0) {
        float count = (float)cntm;
        if (count < 1.f) count = 1.f;
        g_msum[b * Ec + e] = acc / count;
    }
}

// ---------------- per-batch min-max normalize -> Wd ----------------
__global__ void k_wd(const float* __restrict__ W) {
    int b = blockIdx.x;
    int tid = threadIdx.x;
    __shared__ float rmn[256], rmx[256];
    float mn = 1e30f, mx = -1e30f;
    for (int e = tid; e < Ec; e += 256) {
        float v = g_msum[b * Ec + e];
        mn = fminf(mn, v); mx = fmaxf(mx, v);
    }
    rmn[tid] = mn; rmx[tid] = mx;
    __syncthreads();
    for (int s = 128; s > 0; s >>= 1) {
        if (tid < s) {
            rmn[tid] = fminf(rmn[tid], rmn[tid + s]);
            rmx[tid] = fmaxf(rmx[tid], rmx[tid + s]);
        }
        __syncthreads();
    }
    mn = rmn[0]; mx = rmx[0];
    float inv = __fdividef(1.f, mx - mn + EPSc);
    for (int e = tid; e < Ec; e += 256) {
        float v = (g_msum[b * Ec + e] - mn) * inv;
        g_Wd[b * Ec + e] = W[e] * (1.f + LAMc * v);
    }
}

// ---------------- node degree weights -> dvi (warp per (b,n)) ----------------
__global__ void k_dvi() {
    int gid = blockIdx.x * (blockDim.x >> 5) + (threadIdx.x >> 5);
    if (gid >= Bc * Nc) return;
    int n = gid % Nc;
    int b = gid / Nc;
    int lane = threadIdx.x & 31;
    int d = g_node_deg[n];
    float s = 0.f;
    for (int i = lane; i < d; i += 32)
        s += g_Wd[b * Ec + g_node_edges[n * MAXD + i]];
    #pragma unroll
    for (int o = 16; o > 0; o >>= 1) s += __shfl_xor_sync(FULLMASK, s, o);
    if (lane == 0) g_dvi[gid] = rsqrtf(fmaxf(s, EPSc));
}

// ---------------- fold conv into input projection: ipwc = ipw@cw, ipbc = ipb@cw ----------------
__global__ void k_fold(const float* __restrict__ ipw, const float* __restrict__ ipb,
                       const float* __restrict__ cw) {
    int j = threadIdx.x & 31;
    int k = threadIdx.x >> 5;   // 512 threads: k in [0,16)
    float s = 0.f;
    #pragma unroll
    for (int f = 0; f < DMc; f++) s += ipw[k * DMc + f] * cw[f * HCc + j];
    g_ipwc[k * DMc + j] = s;
    if (threadIdx.x < 32) {
        float sb = 0.f;
        #pragma unroll
        for (int f = 0; f < DMc; f++) sb += ipb[f] * cw[f * HCc + j];
        g_ipbc[j] = sb;
    }
}

// ---------------- slice kernel: ys stage -> edge gather (regs) -> node gather -> g_hc ----------------
// one block per (b,t); 512 threads; smem reused between ys and edge features
__global__ __launch_bounds__(512) void k_slice(const float* __restrict__ x,
                                               const float* __restrict__ cbg) {
    extern __shared__ float xs[];            // (Nc+1)*32 floats, reused
    float* sipw = xs + (Nc + 1) * 32;        // 512
    float* sipb = sipw + 512;                // 32
    int bt = blockIdx.x;
    int b = bt / Tc;
    int t = bt % Tc;
    int lane = threadIdx.x & 31;
    int w = threadIdx.x >> 5;

    if (threadIdx.x < 512) sipw[threadIdx.x] = g_ipwc[threadIdx.x];
    if (threadIdx.x < 32) sipb[threadIdx.x] = g_ipbc[threadIdx.x];
    __syncthreads();

    // phase 1: ys = dvi * (x @ ipwc + ipbc)
    const float* xb = x + (size_t)bt * Nc * F_INc;
    float4* xs4 = (float4*)xs;
    for (int i = threadIdx.x; i < (Nc + 1) * 8; i += 512) {
        int n = i >> 3, q = (i & 7) * 4;
        float4 v = make_float4(0.f, 0.f, 0.f, 0.f);
        if (n < Nc) {
            const float* xr = xb + n * F_INc;
            float a0 = sipb[q], a1 = sipb[q + 1], a2 = sipb[q + 2], a3 = sipb[q + 3];
            #pragma unroll
            for (int k = 0; k < F_INc; k++) {
                float xv = xr[k];
                a0 += xv * sipw[k * 32 + q];
                a1 += xv * sipw[k * 32 + q + 1];
                a2 += xv * sipw[k * 32 + q + 2];
                a3 += xv * sipw[k * 32 + q + 3];
            }
            float d = g_dvi[b * Nc + n];
            v = make_float4(a0 * d, a1 * d, a2 * d, a3 * d);
        }
        xs4[i] = v;
    }
    __syncthreads();

    // phase 2: edge gather into registers (warp w owns edges [w*64, w*64+64))
    int e0 = w * 64;
    float u_reg[64];
    #pragma unroll
    for (int el = 0; el < 64; el++) {
        int e = e0 + el;
        float uv = 0.f;
        if (e < Ec) {
            const int4* ip = (const int4*)(g_edge_nodes + e * ESTRIDE);
            int4 a0 = ip[0], a1 = ip[1], a2 = ip[2], a3 = ip[3], a4 = ip[4], a5 = ip[5];
            float p0 = xs[a0.x * 32 + lane] + xs[a1.x * 32 + lane]
                     + xs[a2.x * 32 + lane] + xs[a3.x * 32 + lane]
                     + xs[a4.x * 32 + lane] + xs[a5.x * 32 + lane];
            float p1 = xs[a0.y * 32 + lane] + xs[a1.y * 32 + lane]
                     + xs[a2.y * 32 + lane] + xs[a3.y * 32 + lane]
                     + xs[a4.y * 32 + lane] + xs[a5.y * 32 + lane];
            float p2 = xs[a0.z * 32 + lane] + xs[a1.z * 32 + lane]
                     + xs[a2.z * 32 + lane] + xs[a3.z * 32 + lane]
                     + xs[a4.z * 32 + lane] + xs[a5.z * 32 + lane];
            float p3 = xs[a0.w * 32 + lane] + xs[a1.w * 32 + lane]
                     + xs[a2.w * 32 + lane] + xs[a3.w * 32 + lane]
                     + xs[a4.w * 32 + lane] + xs[a5.w * 32 + lane];
            float sc = __fdividef(g_Wd[b * Ec + e], (float)g_edge_cnt[e]);
            uv = ((p0 + p1) + (p2 + p3)) * sc;
        }
        u_reg[el] = uv;
    }
    __syncthreads();   // all reads of ys complete

    // phase 3: overwrite smem with edge features
    #pragma unroll
    for (int el = 0; el < 64; el++) {
        int e = e0 + el;
        if (e < Ec) xs[e * 32 + lane] = u_reg[el];
    }
    if (threadIdx.x < 32) xs[Nc * 32 + threadIdx.x] = 0.f;  // dummy row for node pad
    __syncthreads();

    // phase 4: node gather + silu -> g_hc  (conv already folded into ys)
    float cbv = cbg[lane];
    for (int n = w; n < Nc; n += 16) {
        int deg = g_node_deg[n];
        int d8 = (deg + 7) & ~7;
        const int* L = g_node_edges + n * MAXD;
        float p0 = 0.f, p1 = 0.f;
        for (int k = 0; k < d8; k += 8) {
            int4 a = *(const int4*)(L + k);
            int4 b2 = *(const int4*)(L + k + 4);
            p0 += xs[a.x * 32 + lane] + xs[a.z * 32 + lane]
                + xs[b2.x * 32 + lane] + xs[b2.z * 32 + lane];
            p1 += xs[a.y * 32 + lane] + xs[a.w * 32 + lane]
                + xs[b2.y * 32 + lane] + xs[b2.w * 32 + lane];
        }
        float z = (p0 + p1) * g_dvi[b * Nc + n] + cbv;
        g_hc[((size_t)(b * Nc + n) * Tc + t) * 32 + lane] = siluf(z);
    }
}

// ---------------- LSTM: smem f32x2 weights, 4 rows/warp, 500 blocks ----------------
__global__ __launch_bounds__(128) void k_lstm3(
    const float* __restrict__ wx, const float* __restrict__ wh,
    const float* __restrict__ lb,
    const float* __restrict__ hw1, const float* __restrict__ hb1,
    const float* __restrict__ hw2, const float* __restrict__ hb2,
    float* __restrict__ out, int Pout) {
    extern __shared__ __align__(16) char smr[];
    u64*   swp  = (u64*)smr;             // 4096: {w01,w23} pairs, index (i*32+lane)*2
    u64*   hb   = swp + 4096;            // 4 warps * 4 rows * 64 = 1024
    float* hw1S = (float*)(hb + 1024);   // 1024
    float* hb1S = hw1S + 1024;           // 32
    float* hw2S = hb1S + 32;             // 384
    float* hb2S = hw2S + 384;            // 16

    int tid = threadIdx.x, lane = tid & 31, w = tid >> 5;
    int rb = blockIdx.x * 16 + w * 4;

    for (int idx = tid; idx < 2048; idx += 128) {
        int i = idx >> 5, l = idx & 31;
        const float* src = (i < 32) ? (wx + i * 128) : (wh + (i - 32) * 128);
        swp[idx * 2]     = packab(src[l], src[32 + l]);
        swp[idx * 2 + 1] = packab(src[64 + l], src[96 + l]);
    }
    for (int i = tid; i < 1024; i += 128) hw1S[i] = hw1[i];
    for (int i = tid; i < 384; i += 128) hw2S[i] = hw2[i];
    if (tid < 32) hb1S[tid] = hb1[tid];
    if (tid < PREDc) hb2S[tid] = hb2[tid];

    u64 bz01 = packab(lb[lane], lb[32 + lane]);
    u64 bz23 = packab(lb[64 + lane], lb[96 + lane]);
    __syncthreads();

    u64* hbw = hb + w * 256;
    const ulonglong2* swp2 = (const ulonglong2*)swp;

    float hcv[4], h[4], c[4];
    #pragma unroll
    for (int r = 0; r < 4; r++) {
        h[r] = 0.f; c[r] = 0.f;
        hcv[r] = g_hc[((size_t)(rb + r) * Tc) * 32 + lane];
    }

    for (int t = 0; t < Tc; t++) {
        #pragma unroll
        for (int r = 0; r < 4; r++) {
            hbw[r * 64 + lane] = pack11(hcv[r]);
            hbw[r * 64 + 32 + lane] = pack11(h[r]);
        }
        float hcn[4];
        if (t + 1 < Tc) {
            #pragma unroll
            for (int r = 0; r < 4; r++)
                hcn[r] = g_hc[((size_t)(rb + r) * Tc + t + 1) * 32 + lane];
        }
        __syncwarp();
        u64 z01[4], z23[4];
        #pragma unroll
        for (int r = 0; r < 4; r++) { z01[r] = bz01; z23[r] = bz23; }
        #pragma unroll 8
        for (int i = 0; i < 64; i += 2) {
            ulonglong2 wA = swp2[i * 32 + lane];
            ulonglong2 wB = swp2[(i + 1) * 32 + lane];
            #pragma unroll
            for (int r = 0; r < 4; r++) {
                ulonglong2 hp = *(const ulonglong2*)&hbw[r * 64 + i];
                ffma2(z01[r], hp.x, wA.x);
                ffma2(z23[r], hp.x, wA.y);
                ffma2(z01[r], hp.y, wB.x);
                ffma2(z23[r], hp.y, wB.y);
            }
        }
        #pragma unroll
        for (int r = 0; r < 4; r++) {
            float2 zif = unpk(z01[r]);
            float2 zgo = unpk(z23[r]);
            float ig = sigmf(zif.x);
            float fg = sigmf(zif.y);
            float gg = tanhf_(zgo.x);
            float og = sigmf(zgo.y);
            c[r] = fg * c[r] + ig * gg;
            h[r] = og * tanhf_(c[r]);
            hcv[r] = hcn[r];
        }
        __syncwarp();
    }

    // head: y = silu(h @ hw1 + hb1) @ hw2 + hb2
    #pragma unroll
    for (int r = 0; r < 4; r++) {
        int row = rb + r;
        int b = row / Nc;
        int n = row % Nc;
        float a = hb1S[lane];
        #pragma unroll 8
        for (int i = 0; i < 32; i++) {
            float hi = __shfl_sync(FULLMASK, h[r], i);
            a += hi * hw1S[i * 32 + lane];
        }
        float y1 = siluf(a);
        float o = (lane < PREDc) ? hb2S[lane] : 0.f;
        #pragma unroll 8
        for (int j = 0; j < 32; j++) {
            float yj = __shfl_sync(FULLMASK, y1, j);
            if (lane < PREDc) o += yj * hw2S[j * PREDc + lane];
        }
        if (lane < Pout) out[((size_t)b * Pout + lane) * Nc + n] = o;
    }
}

// ---------------- launch ----------------
extern "C" void kernel_launch(void* const* d_in, const int* in_sizes, int n_in,
                              void* d_out, int out_size) {
    const float* x       = (const float*)d_in[0];
    const float* xraw    = (const float*)d_in[1];
    const float* W       = (const float*)d_in[3];
    const int*   members = (const int*)d_in[4];
    const int*   centers = (const int*)d_in[5];
    const int*   offsets = (const int*)d_in[6];
    const float* ipw     = (const float*)d_in[7];
    const float* ipb     = (const float*)d_in[8];
    const float* cw      = (const float*)d_in[9];
    const float* cb      = (const float*)d_in[10];
    const float* wx      = (const float*)d_in[11];
    const float* wh      = (const float*)d_in[12];
    const float* lb      = (const float*)d_in[13];
    const float* hw1     = (const float*)d_in[14];
    const float* hb1     = (const float*)d_in[15];
    const float* hw2     = (const float*)d_in[16];
    const float* hb2     = (const float*)d_in[17];
    float* out = (float*)d_out;
    int Pout = out_size / (Bc * Nc);

    int smem_slice = ((Nc + 1) * 32 + 512 + 32) * sizeof(float);          // 130304
    int smem_lstm  = 5120 * sizeof(u64) + 1456 * sizeof(float);           // 46784
    cudaFuncSetAttribute(k_slice, cudaFuncAttributeMaxDynamicSharedMemorySize, smem_slice);
    cudaFuncSetAttribute(k_lstm3, cudaFuncAttributeMaxDynamicSharedMemorySize, smem_lstm);

    k_adj<<<1, 1024>>>(members, centers, offsets);
    k_feat<<<(Bc * Nc * C_RAWc + 255) / 256, 256>>>(xraw);
    k_sim<<<(Bc * Ec + 7) / 8, 256>>>(members, centers, offsets);
    k_wd<<<Bc, 256>>>(W);
    k_dvi<<<(Bc * Nc + 7) / 8, 256>>>();
    k_fold<<<1, 512>>>(ipw, ipb, cw);
    k_slice<<<Bc * Tc, 512, smem_slice>>>(x, cb);
    k_lstm3<<<Bc * Nc / 16, 128, smem_lstm>>>(wx, wh, lb, hw1, hb1, hw2, hb2, out, Pout);
}

// round 8
// speedup vs baseline: 1.2670x; 1.2670x over previous
#include <cuda_runtime.h>
#include <math.h>

#define FULLMASK 0xffffffffu

#define Bc 8
#define Tc 24
#define Nc 1000
#define Ec 1000
#define F_INc 16
#define C_RAWc 8
#define DMc 32
#define HCc 32
#define PREDc 12
#define LAMc 0.3f
#define EPSc 1e-8f
#define MAXD 64
#define ESTRIDE 24     // padded edge member list stride (int4-aligned)

typedef unsigned long long u64;

// ---------------- scratch (device globals; no allocation) ----------------
__device__ int   g_edge_nodes[Ec * ESTRIDE];
__device__ int   g_edge_cnt[Ec];
__device__ int   g_node_edges[Nc * MAXD];
__device__ int   g_node_deg[Nc];
__device__ float g_feat[Bc * Nc * 16];
__device__ float g_msum[Bc * Ec];
__device__ float g_Wd[Bc * Ec];
__device__ float g_dvi[Bc * Nc];
__device__ float g_ipwc[F_INc * DMc];   // folded ipw @ cw
__device__ float g_ipbc[DMc];           // folded ipb @ cw
__device__ float g_hc[(size_t)Bc * Nc * Tc * HCc];   // conv outputs (LSTM inputs)

// ---------------- math helpers ----------------
__device__ __forceinline__ float sigmf(float x) { return __fdividef(1.f, 1.f + __expf(-x)); }
__device__ __forceinline__ float tanhf_(float x) { return 2.f * sigmf(2.f * x) - 1.f; }
__device__ __forceinline__ float siluf(float x) { return x * sigmf(x); }

__device__ __forceinline__ u64 pack11(float x) {
    u64 r; asm("mov.b64 %0, {%1, %1};" : "=l"(r) : "f"(x)); return r;
}
__device__ __forceinline__ u64 packab(float a, float b) {
    u64 r; asm("mov.b64 %0, {%1, %2};" : "=l"(r) : "f"(a), "f"(b)); return r;
}
__device__ __forceinline__ void ffma2(u64& d, u64 a, u64 b) {
    asm("fma.rn.f32x2 %0, %1, %2, %0;" : "+l"(d) : "l"(a), "l"(b));
}
__device__ __forceinline__ u64 add2(u64 a, u64 b) {
    u64 r; asm("add.rn.f32x2 %0, %1, %2;" : "=l"(r) : "l"(a), "l"(b)); return r;
}
__device__ __forceinline__ float2 unpk(u64 v) {
    float2 f; asm("mov.b64 {%0, %1}, %2;" : "=f"(f.x), "=f"(f.y) : "l"(v)); return f;
}

// ---------------- adjacency build ----------------
__global__ void k_zero_deg() {
    int i = blockIdx.x * blockDim.x + threadIdx.x;
    if (i < Nc) g_node_deg[i] = 0;
}

__global__ void k_build_edges(const int* __restrict__ members,
                              const int* __restrict__ centers,
                              const int* __restrict__ offsets) {
    int e = blockIdx.x * blockDim.x + threadIdx.x;
    if (e >= Ec) return;
    int s = offsets[e], t = offsets[e + 1];
    int list[ESTRIDE];
    int cnt = 0;
    for (int m = s; m < t && cnt < ESTRIDE; m++) {
        int n = members[m];
        bool dup = false;
        for (int k = 0; k < cnt; k++) if (list[k] == n) { dup = true; break; }
        if (!dup) list[cnt++] = n;
    }
    {
        int c = centers[e];
        bool dup = false;
        for (int k = 0; k < cnt; k++) if (list[k] == c) { dup = true; break; }
        if (!dup && cnt < ESTRIDE) list[cnt++] = c;
    }
    g_edge_cnt[e] = cnt;
    for (int k = 0; k < cnt; k++) {
        int n = list[k];
        g_edge_nodes[e * ESTRIDE + k] = n;
        int pos = atomicAdd(&g_node_deg[n], 1);
        if (pos < MAXD) g_node_edges[n * MAXD + pos] = e;
    }
    for (int k = cnt; k < ESTRIDE; k++) g_edge_nodes[e * ESTRIDE + k] = Nc;  // dummy zero row
}

__global__ void k_sort_nodes() {
    int n = blockIdx.x * blockDim.x + threadIdx.x;
    if (n >= Nc) return;
    int d = g_node_deg[n];
    if (d > MAXD) d = MAXD;
    g_node_deg[n] = d;
    int* L = g_node_edges + n * MAXD;
    for (int i = 1; i < d; i++) {
        int key = L[i];
        int j = i - 1;
        while (j >= 0 && L[j] > key) { L[j + 1] = L[j]; j--; }
        L[j + 1] = key;
    }
    int d8 = (d + 7) & ~7;
    if (d8 > MAXD) d8 = MAXD;
    for (int i = d; i < d8; i++) L[i] = Ec;  // dummy: smem row 1000 zeroed
}

// ---------------- dynamic features: mean/std over T ----------------
__global__ void k_feat(const float* __restrict__ xraw) {
    int idx = blockIdx.x * blockDim.x + threadIdx.x;
    if (idx >= Bc * Nc * C_RAWc) return;
    int c = idx % C_RAWc;
    int n = (idx / C_RAWc) % Nc;
    int b = idx / (C_RAWc * Nc);
    float s1 = 0.f, s2 = 0.f;
    #pragma unroll
    for (int t = 0; t < Tc; t++) {
        float v = xraw[((b * Tc + t) * Nc + n) * C_RAWc + c];
        s1 += v; s2 += v * v;
    }
    float mean = s1 * (1.f / Tc);
    float var = s2 * (1.f / Tc) - mean * mean;
    if (var < 0.f) var = 0.f;
    g_feat[(b * Nc + n) * 16 + c] = mean;
    g_feat[(b * Nc + n) * 16 + C_RAWc + c] = sqrtf(var);
}

// ---------------- per-edge mean similarity (warp per (b,e)) ----------------
__global__ void k_sim(const int* __restrict__ members,
                      const int* __restrict__ centers,
                      const int* __restrict__ offsets) {
    int gid = blockIdx.x * (blockDim.x >> 5) + (threadIdx.x >> 5);
    if (gid >= Bc * Ec) return;
    int e = gid % Ec;
    int b = gid / Ec;
    int lane = threadIdx.x & 31;
    int s = offsets[e];
    int cntm = offsets[e + 1] - s;
    int cn = centers[e];
    const float4* cf4 = (const float4*)(g_feat + (b * Nc + cn) * 16);
    float4 c0 = cf4[0], c1 = cf4[1], c2 = cf4[2], c3 = cf4[3];
    float cn2 = c0.x*c0.x + c0.y*c0.y + c0.z*c0.z + c0.w*c0.w
              + c1.x*c1.x + c1.y*c1.y + c1.z*c1.z + c1.w*c1.w
              + c2.x*c2.x + c2.y*c2.y + c2.z*c2.z + c2.w*c2.w
              + c3.x*c3.x + c3.y*c3.y + c3.z*c3.z + c3.w*c3.w;
    float cnorm = sqrtf(cn2);
    float acc = 0.f;
    for (int m = lane; m < cntm; m += 32) {
        int n = members[s + m];
        const float4* mf4 = (const float4*)(g_feat + (b * Nc + n) * 16);
        float4 m0 = mf4[0], m1 = mf4[1], m2 = mf4[2], m3 = mf4[3];
        float dot = m0.x*c0.x + m0.y*c0.y + m0.z*c0.z + m0.w*c0.w
                  + m1.x*c1.x + m1.y*c1.y + m1.z*c1.z + m1.w*c1.w
                  + m2.x*c2.x + m2.y*c2.y + m2.z*c2.z + m2.w*c2.w
                  + m3.x*c3.x + m3.y*c3.y + m3.z*c3.z + m3.w*c3.w;
        float mn2 = m0.x*m0.x + m0.y*m0.y + m0.z*m0.z + m0.w*m0.w
                  + m1.x*m1.x + m1.y*m1.y + m1.z*m1.z + m1.w*m1.w
                  + m2.x*m2.x + m2.y*m2.y + m2.z*m2.z + m2.w*m2.w
                  + m3.x*m3.x + m3.y*m3.y + m3.z*m3.z + m3.w*m3.w;
        float sim = dot / (sqrtf(mn2) * cnorm + EPSc);
        acc += fminf(fmaxf(sim, 0.f), 1.f);
    }
    #pragma unroll
    for (int o = 16; o > 0; o >>= 1) acc += __shfl_xor_sync(FULLMASK, acc, o);
    if (lane == 0) {
        float count = (float)cntm;
        if (count < 1.f) count = 1.f;
        g_msum[b * Ec + e] = acc / count;
    }
}

// ---------------- fused: per-batch Wd (min/max) + dvi; block 8 does the conv fold ----------------
__global__ __launch_bounds__(256) void k_wdf(const float* __restrict__ W,
                                             const float* __restrict__ ipw,
                                             const float* __restrict__ ipb,
                                             const float* __restrict__ cw) {
    __shared__ float sWd[Ec];
    __shared__ float rmn[256], rmx[256];
    int b = blockIdx.x;
    int tid = threadIdx.x;

    if (b < Bc) {
        float mn = 1e30f, mx = -1e30f;
        for (int e = tid; e < Ec; e += 256) {
            float v = g_msum[b * Ec + e];
            mn = fminf(mn, v); mx = fmaxf(mx, v);
        }
        rmn[tid] = mn; rmx[tid] = mx;
        __syncthreads();
        for (int s = 128; s > 0; s >>= 1) {
            if (tid < s) {
                rmn[tid] = fminf(rmn[tid], rmn[tid + s]);
                rmx[tid] = fmaxf(rmx[tid], rmx[tid + s]);
            }
            __syncthreads();
        }
        mn = rmn[0]; mx = rmx[0];
        float inv = __fdividef(1.f, mx - mn + EPSc);
        for (int e = tid; e < Ec; e += 256) {
            float v = (g_msum[b * Ec + e] - mn) * inv;
            float wd = W[e] * (1.f + LAMc * v);
            sWd[e] = wd;
            g_Wd[b * Ec + e] = wd;
        }
        __syncthreads();
        // dvi from smem-resident Wd
        for (int n = tid; n < Nc; n += 256) {
            int d = g_node_deg[n];
            const int* L = g_node_edges + n * MAXD;
            float s = 0.f;
            for (int i = 0; i < d; i++) s += sWd[L[i]];
            g_dvi[b * Nc + n] = rsqrtf(fmaxf(s, EPSc));
        }
    } else {
        // fold conv into input projection: ipwc = ipw@cw, ipbc = ipb@cw
        for (int it = tid; it < F_INc * DMc; it += 256) {
            int k = it >> 5, j = it & 31;
            float s = 0.f;
            #pragma unroll
            for (int f = 0; f < DMc; f++) s += ipw[k * DMc + f] * cw[f * HCc + j];
            g_ipwc[it] = s;
        }
        if (tid < 32) {
            float sb = 0.f;
            #pragma unroll
            for (int f = 0; f < DMc; f++) sb += ipb[f] * cw[f * HCc + tid];
            g_ipbc[tid] = sb;
        }
    }
}

// ---------------- slice kernel: ys stage -> edge gather (regs) -> node gather -> g_hc ----------------
// one block per (b,t); 512 threads; smem reused between ys and edge features
__global__ __launch_bounds__(512) void k_slice(const float* __restrict__ x,
                                               const float* __restrict__ cbg) {
    extern __shared__ float xs[];            // (Nc+1)*32 floats, reused
    float* sipw = xs + (Nc + 1) * 32;        // 512
    float* sipb = sipw + 512;                // 32
    int bt = blockIdx.x;
    int b = bt / Tc;
    int t = bt % Tc;
    int lane = threadIdx.x & 31;
    int w = threadIdx.x >> 5;

    if (threadIdx.x < 512) sipw[threadIdx.x] = g_ipwc[threadIdx.x];
    if (threadIdx.x < 32) sipb[threadIdx.x] = g_ipbc[threadIdx.x];
    __syncthreads();

    // phase 1: ys = dvi * (x @ ipwc + ipbc)
    const float* xb = x + (size_t)bt * Nc * F_INc;
    float4* xs4 = (float4*)xs;
    for (int i = threadIdx.x; i < (Nc + 1) * 8; i += 512) {
        int n = i >> 3, q = (i & 7) * 4;
        float4 v = make_float4(0.f, 0.f, 0.f, 0.f);
        if (n < Nc) {
            const float* xr = xb + n * F_INc;
            float a0 = sipb[q], a1 = sipb[q + 1], a2 = sipb[q + 2], a3 = sipb[q + 3];
            #pragma unroll
            for (int k = 0; k < F_INc; k++) {
                float xv = xr[k];
                a0 += xv * sipw[k * 32 + q];
                a1 += xv * sipw[k * 32 + q + 1];
                a2 += xv * sipw[k * 32 + q + 2];
                a3 += xv * sipw[k * 32 + q + 3];
            }
            float d = g_dvi[b * Nc + n];
            v = make_float4(a0 * d, a1 * d, a2 * d, a3 * d);
        }
        xs4[i] = v;
    }
    __syncthreads();

    // phase 2: edge gather into registers (warp w owns edges [w*64, w*64+64))
    int e0 = w * 64;
    float u_reg[64];
    #pragma unroll
    for (int el = 0; el < 64; el++) {
        int e = e0 + el;
        float uv = 0.f;
        if (e < Ec) {
            const int4* ip = (const int4*)(g_edge_nodes + e * ESTRIDE);
            int4 a0 = ip[0], a1 = ip[1], a2 = ip[2], a3 = ip[3], a4 = ip[4], a5 = ip[5];
            float p0 = xs[a0.x * 32 + lane] + xs[a1.x * 32 + lane]
                     + xs[a2.x * 32 + lane] + xs[a3.x * 32 + lane]
                     + xs[a4.x * 32 + lane] + xs[a5.x * 32 + lane];
            float p1 = xs[a0.y * 32 + lane] + xs[a1.y * 32 + lane]
                     + xs[a2.y * 32 + lane] + xs[a3.y * 32 + lane]
                     + xs[a4.y * 32 + lane] + xs[a5.y * 32 + lane];
            float p2 = xs[a0.z * 32 + lane] + xs[a1.z * 32 + lane]
                     + xs[a2.z * 32 + lane] + xs[a3.z * 32 + lane]
                     + xs[a4.z * 32 + lane] + xs[a5.z * 32 + lane];
            float p3 = xs[a0.w * 32 + lane] + xs[a1.w * 32 + lane]
                     + xs[a2.w * 32 + lane] + xs[a3.w * 32 + lane]
                     + xs[a4.w * 32 + lane] + xs[a5.w * 32 + lane];
            float sc = __fdividef(g_Wd[b * Ec + e], (float)g_edge_cnt[e]);
            uv = ((p0 + p1) + (p2 + p3)) * sc;
        }
        u_reg[el] = uv;
    }
    __syncthreads();   // all reads of ys complete

    // phase 3: overwrite smem with edge features
    #pragma unroll
    for (int el = 0; el < 64; el++) {
        int e = e0 + el;
        if (e < Ec) xs[e * 32 + lane] = u_reg[el];
    }
    if (threadIdx.x < 32) xs[Nc * 32 + threadIdx.x] = 0.f;  // dummy row for node pad
    __syncthreads();

    // phase 4: node gather + silu -> g_hc  (conv already folded into ys)
    float cbv = cbg[lane];
    for (int n = w; n < Nc; n += 16) {
        int deg = g_node_deg[n];
        int d8 = (deg + 7) & ~7;
        const int* L = g_node_edges + n * MAXD;
        float p0 = 0.f, p1 = 0.f;
        for (int k = 0; k < d8; k += 8) {
            int4 a = *(const int4*)(L + k);
            int4 b2 = *(const int4*)(L + k + 4);
            p0 += xs[a.x * 32 + lane] + xs[a.z * 32 + lane]
                + xs[b2.x * 32 + lane] + xs[b2.z * 32 + lane];
            p1 += xs[a.y * 32 + lane] + xs[a.w * 32 + lane]
                + xs[b2.y * 32 + lane] + xs[b2.w * 32 + lane];
        }
        float z = (p0 + p1) * g_dvi[b * Nc + n] + cbv;
        g_hc[((size_t)(b * Nc + n) * Tc + t) * 32 + lane] = siluf(z);
    }
}

// ---------------- LSTM: split-K warp pairs (work-conserving), 8 rows/pair ----------------
// block = 256 thr = 8 warps = 4 pairs; pair p rows [blk*32+p*8, +8); role 0: K in [0,32) (hc),
// role 1: K in [32,64) (h). Each warp owns 4 rows' state/activations; partials via smem.
__global__ __launch_bounds__(256) void k_lstm4(
    const float* __restrict__ wx, const float* __restrict__ wh,
    const float* __restrict__ lb,
    const float* __restrict__ hw1, const float* __restrict__ hb1,
    const float* __restrict__ hw2, const float* __restrict__ hb2,
    float* __restrict__ out, int Pout) {
    extern __shared__ __align__(16) char smr[];
    u64*        swp   = (u64*)smr;                 // 4096: {w01,w23} pairs
    u64*        hball = swp + 4096;                // 4 pairs * 8 rows * 64 = 2048
    ulonglong2* zball = (ulonglong2*)(hball + 2048); // 4 pairs * 8 rows * 32 lanes
    float*      hw1S  = (float*)(zball + 1024);    // 1024
    float*      hb1S  = hw1S + 1024;               // 32
    float*      hw2S  = hb1S + 32;                 // 384
    float*      hb2S  = hw2S + 384;                // 16

    int tid = threadIdx.x, lane = tid & 31, w = tid >> 5;
    int pair = w >> 1, role = w & 1;
    int rb = blockIdx.x * 32 + pair * 8;   // pair's first global row
    int own = role * 4;                    // owned row offset within pair

    for (int idx = tid; idx < 2048; idx += 256) {
        int i = idx >> 5, l = idx & 31;
        const float* src = (i < 32) ? (wx + i * 128) : (wh + (i - 32) * 128);
        swp[idx * 2]     = packab(src[l], src[32 + l]);
        swp[idx * 2 + 1] = packab(src[64 + l], src[96 + l]);
    }
    for (int i = tid; i < 1024; i += 256) hw1S[i] = hw1[i];
    for (int i = tid; i < 384; i += 256) hw2S[i] = hw2[i];
    if (tid < 32) hb1S[tid] = hb1[tid];
    if (tid < PREDc) hb2S[tid] = hb2[tid];

    u64 bz01 = packab(lb[lane], lb[32 + lane]);
    u64 bz23 = packab(lb[64 + lane], lb[96 + lane]);

    u64*        hbw = hball + pair * 512;          // [r*64 + i]
    ulonglong2* zbp = zball + pair * 256;          // [r*32 + lane]
    const ulonglong2* swp2 = (const ulonglong2*)swp;
    int koff = role * 32;

    // init: owned rows' h(-1)=0 and hc(0)
    float h[4], c[4], hcv[4];
    #pragma unroll
    for (int q = 0; q < 4; q++) {
        h[q] = 0.f; c[q] = 0.f;
        hcv[q] = g_hc[((size_t)(rb + own + q) * Tc) * 32 + lane];
        hbw[(own + q) * 64 + lane] = pack11(hcv[q]);
        hbw[(own + q) * 64 + 32 + lane] = pack11(0.f);
    }
    __syncthreads();

    for (int t = 0; t < Tc; t++) {
        // K-half GEMM for all 8 rows of the pair
        u64 z01[8], z23[8];
        #pragma unroll
        for (int r = 0; r < 8; r++) {
            z01[r] = role ? 0ull : bz01;
            z23[r] = role ? 0ull : bz23;
        }
        #pragma unroll 8
        for (int i = 0; i < 32; i += 2) {
            ulonglong2 wA = swp2[(koff + i) * 32 + lane];
            ulonglong2 wB = swp2[(koff + i + 1) * 32 + lane];
            #pragma unroll
            for (int r = 0; r < 8; r++) {
                ulonglong2 hp = *(const ulonglong2*)&hbw[r * 64 + koff + i];
                ffma2(z01[r], hp.x, wA.x);
                ffma2(z23[r], hp.x, wA.y);
                ffma2(z01[r], hp.y, wB.x);
                ffma2(z23[r], hp.y, wB.y);
            }
        }
        // store partials for the 4 NON-owned rows
        int nown = own ^ 4;
        #pragma unroll
        for (int q = 0; q < 4; q++) {
            int r = nown + q;
            zbp[r * 32 + lane] = make_ulonglong2(z01[r], z23[r]);
        }
        __syncthreads();
        // combine + activations for owned rows; prefetch hc(t+1)
        float hcn[4];
        if (t + 1 < Tc) {
            #pragma unroll
            for (int q = 0; q < 4; q++)
                hcn[q] = g_hc[((size_t)(rb + own + q) * Tc + t + 1) * 32 + lane];
        }
        #pragma unroll
        for (int q = 0; q < 4; q++) {
            int r = own + q;
            ulonglong2 pp = zbp[r * 32 + lane];
            float2 zif = unpk(add2(z01[r], pp.x));
            float2 zgo = unpk(add2(z23[r], pp.y));
            float ig = sigmf(zif.x);
            float fg = sigmf(zif.y);
            float gg = tanhf_(zgo.x);
            float og = sigmf(zgo.y);
            c[q] = fg * c[q] + ig * gg;
            h[q] = og * tanhf_(c[q]);
            hbw[r * 64 + 32 + lane] = pack11(h[q]);
            if (t + 1 < Tc) hbw[r * 64 + lane] = pack11(hcn[q]);
        }
        __syncthreads();
    }

    // head for owned rows: y = silu(h @ hw1 + hb1) @ hw2 + hb2
    #pragma unroll
    for (int q = 0; q < 4; q++) {
        int row = rb + own + q;
        int b = row / Nc;
        int n = row % Nc;
        float a = hb1S[lane];
        #pragma unroll 8
        for (int i = 0; i < 32; i++) {
            float hi = __shfl_sync(FULLMASK, h[q], i);
            a += hi * hw1S[i * 32 + lane];
        }
        float y1 = siluf(a);
        float o = (lane < PREDc) ? hb2S[lane] : 0.f;
        #pragma unroll 8
        for (int j = 0; j < 32; j++) {
            float yj = __shfl_sync(FULLMASK, y1, j);
            if (lane < PREDc) o += yj * hw2S[j * PREDc + lane];
        }
        if (lane < Pout) out[((size_t)b * Pout + lane) * Nc + n] = o;
    }
}

// ---------------- launch ----------------
extern "C" void kernel_launch(void* const* d_in, const int* in_sizes, int n_in,
                              void* d_out, int out_size) {
    const float* x       = (const float*)d_in[0];
    const float* xraw    = (const float*)d_in[1];
    const float* W       = (const float*)d_in[3];
    const int*   members = (const int*)d_in[4];
    const int*   centers = (const int*)d_in[5];
    const int*   offsets = (const int*)d_in[6];
    const float* ipw     = (const float*)d_in[7];
    const float* ipb     = (const float*)d_in[8];
    const float* cw      = (const float*)d_in[9];
    const float* cb      = (const float*)d_in[10];
    const float* wx      = (const float*)d_in[11];
    const float* wh      = (const float*)d_in[12];
    const float* lb      = (const float*)d_in[13];
    const float* hw1     = (const float*)d_in[14];
    const float* hb1     = (const float*)d_in[15];
    const float* hw2     = (const float*)d_in[16];
    const float* hb2     = (const float*)d_in[17];
    float* out = (float*)d_out;
    int Pout = out_size / (Bc * Nc);

    int smem_slice = ((Nc + 1) * 32 + 512 + 32) * sizeof(float);          // 130304
    int smem_lstm  = 6144 * sizeof(u64) + 1024 * sizeof(ulonglong2) + 1456 * sizeof(float);  // 71360
    cudaFuncSetAttribute(k_slice, cudaFuncAttributeMaxDynamicSharedMemorySize, smem_slice);
    cudaFuncSetAttribute(k_lstm4, cudaFuncAttributeMaxDynamicSharedMemorySize, smem_lstm);

    k_zero_deg<<<4, 256>>>();
    k_build_edges<<<4, 256>>>(members, centers, offsets);
    k_sort_nodes<<<4, 256>>>();
    k_feat<<<(Bc * Nc * C_RAWc + 255) / 256, 256>>>(xraw);
    k_sim<<<(Bc * Ec + 7) / 8, 256>>>(members, centers, offsets);
    k_wdf<<<Bc + 1, 256>>>(W, ipw, ipb, cw);
    k_slice<<<Bc * Tc, 512, smem_slice>>>(x, cb);
    k_lstm4<<<Bc * Nc / 32, 256, smem_lstm>>>(wx, wh, lb, hw1, hb1, hw2, hb2, out, Pout);
}

// round 9
// speedup vs baseline: 1.3657x; 1.0779x over previous
#include <cuda_runtime.h>
#include <math.h>

#define FULLMASK 0xffffffffu

#define Bc 8
#define Tc 24
#define Nc 1000
#define Ec 1000
#define F_INc 16
#define C_RAWc 8
#define DMc 32
#define HCc 32
#define PREDc 12
#define LAMc 0.3f
#define EPSc 1e-8f
#define MAXD 64
#define ESTRIDE 24     // padded edge member list stride (int4-aligned)

typedef unsigned long long u64;

// ---------------- scratch (device globals; no allocation) ----------------
__device__ int   g_edge_nodes[Ec * ESTRIDE];
__device__ int   g_edge_cnt[Ec];
__device__ int   g_node_edges[Nc * MAXD];
__device__ int   g_node_deg[Nc];
__device__ float g_feat[Bc * Nc * 16];
__device__ float g_msum[Bc * Ec];
__device__ float g_Wd[Bc * Ec];
__device__ float g_dvi[Bc * Nc];
__device__ float g_ipwc[F_INc * DMc];   // folded ipw @ cw
__device__ float g_ipbc[DMc];           // folded ipb @ cw
__device__ float g_hc[(size_t)Bc * Nc * Tc * HCc];   // conv outputs (LSTM inputs)

// ---------------- math helpers ----------------
__device__ __forceinline__ float sigmf(float x) { return __fdividef(1.f, 1.f + __expf(-x)); }
__device__ __forceinline__ float tanhf_(float x) { return 2.f * sigmf(2.f * x) - 1.f; }
__device__ __forceinline__ float siluf(float x) { return x * sigmf(x); }

__device__ __forceinline__ u64 pack11(float x) {
    u64 r; asm("mov.b64 %0, {%1, %1};" : "=l"(r) : "f"(x)); return r;
}
__device__ __forceinline__ u64 packab(float a, float b) {
    u64 r; asm("mov.b64 %0, {%1, %2};" : "=l"(r) : "f"(a), "f"(b)); return r;
}
__device__ __forceinline__ void ffma2(u64& d, u64 a, u64 b) {
    asm("fma.rn.f32x2 %0, %1, %2, %0;" : "+l"(d) : "l"(a), "l"(b));
}
__device__ __forceinline__ float2 unpk(u64 v) {
    float2 f; asm("mov.b64 {%0, %1}, %2;" : "=f"(f.x), "=f"(f.y) : "l"(v)); return f;
}

// ---------------- adjacency build ----------------
__global__ void k_zero_deg() {
    int i = blockIdx.x * blockDim.x + threadIdx.x;
    if (i < Nc) g_node_deg[i] = 0;
}

__global__ void k_build_edges(const int* __restrict__ members,
                              const int* __restrict__ centers,
                              const int* __restrict__ offsets) {
    int e = blockIdx.x * blockDim.x + threadIdx.x;
    if (e >= Ec) return;
    int s = offsets[e], t = offsets[e + 1];
    int list[ESTRIDE];
    int cnt = 0;
    for (int m = s; m < t && cnt < ESTRIDE; m++) {
        int n = members[m];
        bool dup = false;
        for (int k = 0; k < cnt; k++) if (list[k] == n) { dup = true; break; }
        if (!dup) list[cnt++] = n;
    }
    {
        int c = centers[e];
        bool dup = false;
        for (int k = 0; k < cnt; k++) if (list[k] == c) { dup = true; break; }
        if (!dup && cnt < ESTRIDE) list[cnt++] = c;
    }
    g_edge_cnt[e] = cnt;
    for (int k = 0; k < cnt; k++) {
        int n = list[k];
        g_edge_nodes[e * ESTRIDE + k] = n;
        int pos = atomicAdd(&g_node_deg[n], 1);
        if (pos < MAXD) g_node_edges[n * MAXD + pos] = e;
    }
    for (int k = cnt; k < ESTRIDE; k++) g_edge_nodes[e * ESTRIDE + k] = Nc;  // dummy zero row
}

__global__ void k_sort_nodes() {
    int n = blockIdx.x * blockDim.x + threadIdx.x;
    if (n >= Nc) return;
    int d = g_node_deg[n];
    if (d > MAXD) d = MAXD;
    g_node_deg[n] = d;
    int* L = g_node_edges + n * MAXD;
    for (int i = 1; i < d; i++) {
        int key = L[i];
        int j = i - 1;
        while (j >= 0 && L[j] > key) { L[j + 1] = L[j]; j--; }
        L[j + 1] = key;
    }
    int d8 = (d + 7) & ~7;
    if (d8 > MAXD) d8 = MAXD;
    for (int i = d; i < d8; i++) L[i] = Ec;  // dummy: smem row 1000 zeroed
}

// ---------------- dynamic features: mean/std over T ----------------
__global__ void k_feat(const float* __restrict__ xraw) {
    int idx = blockIdx.x * blockDim.x + threadIdx.x;
    if (idx >= Bc * Nc * C_RAWc) return;
    int c = idx % C_RAWc;
    int n = (idx / C_RAWc) % Nc;
    int b = idx / (C_RAWc * Nc);
    float s1 = 0.f, s2 = 0.f;
    #pragma unroll
    for (int t = 0; t < Tc; t++) {
        float v = xraw[((b * Tc + t) * Nc + n) * C_RAWc + c];
        s1 += v; s2 += v * v;
    }
    float mean = s1 * (1.f / Tc);
    float var = s2 * (1.f / Tc) - mean * mean;
    if (var < 0.f) var = 0.f;
    g_feat[(b * Nc + n) * 16 + c] = mean;
    g_feat[(b * Nc + n) * 16 + C_RAWc + c] = sqrtf(var);
}

// ---------------- per-edge mean similarity (warp per (b,e)) ----------------
__global__ void k_sim(const int* __restrict__ members,
                      const int* __restrict__ centers,
                      const int* __restrict__ offsets) {
    int gid = blockIdx.x * (blockDim.x >> 5) + (threadIdx.x >> 5);
    if (gid >= Bc * Ec) return;
    int e = gid % Ec;
    int b = gid / Ec;
    int lane = threadIdx.x & 31;
    int s = offsets[e];
    int cntm = offsets[e + 1] - s;
    int cn = centers[e];
    const float4* cf4 = (const float4*)(g_feat + (b * Nc + cn) * 16);
    float4 c0 = cf4[0], c1 = cf4[1], c2 = cf4[2], c3 = cf4[3];
    float cn2 = c0.x*c0.x + c0.y*c0.y + c0.z*c0.z + c0.w*c0.w
              + c1.x*c1.x + c1.y*c1.y + c1.z*c1.z + c1.w*c1.w
              + c2.x*c2.x + c2.y*c2.y + c2.z*c2.z + c2.w*c2.w
              + c3.x*c3.x + c3.y*c3.y + c3.z*c3.z + c3.w*c3.w;
    float cnorm = sqrtf(cn2);
    float acc = 0.f;
    for (int m = lane; m < cntm; m += 32) {
        int n = members[s + m];
        const float4* mf4 = (const float4*)(g_feat + (b * Nc + n) * 16);
        float4 m0 = mf4[0], m1 = mf4[1], m2 = mf4[2], m3 = mf4[3];
        float dot = m0.x*c0.x + m0.y*c0.y + m0.z*c0.z + m0.w*c0.w
                  + m1.x*c1.x + m1.y*c1.y + m1.z*c1.z + m1.w*c1.w
                  + m2.x*c2.x + m2.y*c2.y + m2.z*c2.z + m2.w*c2.w
                  + m3.x*c3.x + m3.y*c3.y + m3.z*c3.z + m3.w*c3.w;
        float mn2 = m0.x*m0.x + m0.y*m0.y + m0.z*m0.z + m0.w*m0.w
                  + m1.x*m1.x + m1.y*m1.y + m1.z*m1.z + m1.w*m1.w
                  + m2.x*m2.x + m2.y*m2.y + m2.z*m2.z + m2.w*m2.w
                  + m3.x*m3.x + m3.y*m3.y + m3.z*m3.z + m3.w*m3.w;
        float sim = dot / (sqrtf(mn2) * cnorm + EPSc);
        acc += fminf(fmaxf(sim, 0.f), 1.f);
    }
    #pragma unroll
    for (int o = 16; o > 0; o >>= 1) acc += __shfl_xor_sync(FULLMASK, acc, o);
    if (lane == 0) {
        float count = (float)cntm;
        if (count < 1.f) count = 1.f;
        g_msum[b * Ec + e] = acc / count;
    }
}

// ---------------- fused: per-batch Wd (min/max) + dvi; block 8 does the conv fold ----------------
__global__ __launch_bounds__(256) void k_wdf(const float* __restrict__ W,
                                             const float* __restrict__ ipw,
                                             const float* __restrict__ ipb,
                                             const float* __restrict__ cw) {
    __shared__ float sWd[Ec];
    __shared__ float rmn[256], rmx[256];
    int b = blockIdx.x;
    int tid = threadIdx.x;

    if (b < Bc) {
        float mn = 1e30f, mx = -1e30f;
        for (int e = tid; e < Ec; e += 256) {
            float v = g_msum[b * Ec + e];
            mn = fminf(mn, v); mx = fmaxf(mx, v);
        }
        rmn[tid] = mn; rmx[tid] = mx;
        __syncthreads();
        for (int s = 128; s > 0; s >>= 1) {
            if (tid < s) {
                rmn[tid] = fminf(rmn[tid], rmn[tid + s]);
                rmx[tid] = fmaxf(rmx[tid], rmx[tid + s]);
            }
            __syncthreads();
        }
        mn = rmn[0]; mx = rmx[0];
        float inv = __fdividef(1.f, mx - mn + EPSc);
        for (int e = tid; e < Ec; e += 256) {
            float v = (g_msum[b * Ec + e] - mn) * inv;
            float wd = W[e] * (1.f + LAMc * v);
            sWd[e] = wd;
            g_Wd[b * Ec + e] = wd;
        }
        __syncthreads();
        // dvi from smem-resident Wd (lists sorted -> deterministic order)
        for (int n = tid; n < Nc; n += 256) {
            int d = g_node_deg[n];
            const int* L = g_node_edges + n * MAXD;
            float s = 0.f;
            for (int i = 0; i < d; i++) s += sWd[L[i]];
            g_dvi[b * Nc + n] = rsqrtf(fmaxf(s, EPSc));
        }
    } else {
        // fold conv into input projection: ipwc = ipw@cw, ipbc = ipb@cw
        for (int it = tid; it < F_INc * DMc; it += 256) {
            int k = it >> 5, j = it & 31;
            float s = 0.f;
            #pragma unroll
            for (int f = 0; f < DMc; f++) s += ipw[k * DMc + f] * cw[f * HCc + j];
            g_ipwc[it] = s;
        }
        if (tid < 32) {
            float sb = 0.f;
            #pragma unroll
            for (int f = 0; f < DMc; f++) sb += ipb[f] * cw[f * HCc + tid];
            g_ipbc[tid] = sb;
        }
    }
}

// ---------------- slice kernel: ys stage -> edge gather (regs) -> node gather -> g_hc ----------------
// one block per (b,t); 512 threads; smem reused between ys and edge features
__global__ __launch_bounds__(512) void k_slice(const float* __restrict__ x,
                                               const float* __restrict__ cbg) {
    extern __shared__ float xs[];            // (Nc+1)*32 floats, reused
    float* sipw = xs + (Nc + 1) * 32;        // 512
    float* sipb = sipw + 512;                // 32
    int bt = blockIdx.x;
    int b = bt / Tc;
    int t = bt % Tc;
    int lane = threadIdx.x & 31;
    int w = threadIdx.x >> 5;

    if (threadIdx.x < 512) sipw[threadIdx.x] = g_ipwc[threadIdx.x];
    if (threadIdx.x < 32) sipb[threadIdx.x] = g_ipbc[threadIdx.x];
    __syncthreads();

    // phase 1: ys = dvi * (x @ ipwc + ipbc)
    const float* xb = x + (size_t)bt * Nc * F_INc;
    float4* xs4 = (float4*)xs;
    for (int i = threadIdx.x; i < (Nc + 1) * 8; i += 512) {
        int n = i >> 3, q = (i & 7) * 4;
        float4 v = make_float4(0.f, 0.f, 0.f, 0.f);
        if (n < Nc) {
            const float* xr = xb + n * F_INc;
            float a0 = sipb[q], a1 = sipb[q + 1], a2 = sipb[q + 2], a3 = sipb[q + 3];
            #pragma unroll
            for (int k = 0; k < F_INc; k++) {
                float xv = xr[k];
                a0 += xv * sipw[k * 32 + q];
                a1 += xv * sipw[k * 32 + q + 1];
                a2 += xv * sipw[k * 32 + q + 2];
                a3 += xv * sipw[k * 32 + q + 3];
            }
            float d = g_dvi[b * Nc + n];
            v = make_float4(a0 * d, a1 * d, a2 * d, a3 * d);
        }
        xs4[i] = v;
    }
    __syncthreads();

    // phase 2: edge gather into registers (warp w owns edges [w*64, w*64+64))
    int e0 = w * 64;
    float u_reg[64];
    #pragma unroll
    for (int el = 0; el < 64; el++) {
        int e = e0 + el;
        float uv = 0.f;
        if (e < Ec) {
            const int4* ip = (const int4*)(g_edge_nodes + e * ESTRIDE);
            int4 a0 = ip[0], a1 = ip[1], a2 = ip[2], a3 = ip[3], a4 = ip[4], a5 = ip[5];
            float p0 = xs[a0.x * 32 + lane] + xs[a1.x * 32 + lane]
                     + xs[a2.x * 32 + lane] + xs[a3.x * 32 + lane]
                     + xs[a4.x * 32 + lane] + xs[a5.x * 32 + lane];
            float p1 = xs[a0.y * 32 + lane] + xs[a1.y * 32 + lane]
                     + xs[a2.y * 32 + lane] + xs[a3.y * 32 + lane]
                     + xs[a4.y * 32 + lane] + xs[a5.y * 32 + lane];
            float p2 = xs[a0.z * 32 + lane] + xs[a1.z * 32 + lane]
                     + xs[a2.z * 32 + lane] + xs[a3.z * 32 + lane]
                     + xs[a4.z * 32 + lane] + xs[a5.z * 32 + lane];
            float p3 = xs[a0.w * 32 + lane] + xs[a1.w * 32 + lane]
                     + xs[a2.w * 32 + lane] + xs[a3.w * 32 + lane]
                     + xs[a4.w * 32 + lane] + xs[a5.w * 32 + lane];
            float sc = __fdividef(g_Wd[b * Ec + e], (float)g_edge_cnt[e]);
            uv = ((p0 + p1) + (p2 + p3)) * sc;
        }
        u_reg[el] = uv;
    }
    __syncthreads();   // all reads of ys complete

    // phase 3: overwrite smem with edge features
    #pragma unroll
    for (int el = 0; el < 64; el++) {
        int e = e0 + el;
        if (e < Ec) xs[e * 32 + lane] = u_reg[el];
    }
    if (threadIdx.x < 32) xs[Nc * 32 + threadIdx.x] = 0.f;  // dummy row for node pad
    __syncthreads();

    // phase 4: node gather + silu -> g_hc  (conv already folded into ys)
    float cbv = cbg[lane];
    for (int n = w; n < Nc; n += 16) {
        int deg = g_node_deg[n];
        int d8 = (deg + 7) & ~7;
        const int* L = g_node_edges + n * MAXD;
        float p0 = 0.f, p1 = 0.f;
        for (int k = 0; k < d8; k += 8) {
            int4 a = *(const int4*)(L + k);
            int4 b2 = *(const int4*)(L + k + 4);
            p0 += xs[a.x * 32 + lane] + xs[a.z * 32 + lane]
                + xs[b2.x * 32 + lane] + xs[b2.z * 32 + lane];
            p1 += xs[a.y * 32 + lane] + xs[a.w * 32 + lane]
                + xs[b2.y * 32 + lane] + xs[b2.w * 32 + lane];
        }
        float z = (p0 + p1) * g_dvi[b * Nc + n] + cbv;
        g_hc[((size_t)(b * Nc + n) * Tc + t) * 32 + lane] = siluf(z);
    }
}

// ---------------- LSTM: smem f32x2 weights, 8 rows/warp, 8 warps/block, 125 blocks ----------------
__global__ __launch_bounds__(256) void k_lstm3(
    const float* __restrict__ wx, const float* __restrict__ wh,
    const float* __restrict__ lb,
    const float* __restrict__ hw1, const float* __restrict__ hb1,
    const float* __restrict__ hw2, const float* __restrict__ hb2,
    float* __restrict__ out, int Pout) {
    extern __shared__ __align__(16) char smr[];
    u64*   swp  = (u64*)smr;             // 4096: {w01,w23} pairs, index (i*32+lane)*2
    u64*   hb   = swp + 4096;            // 8 warps * 8 rows * 64 = 4096
    float* hw1S = (float*)(hb + 4096);   // 1024
    float* hb1S = hw1S + 1024;           // 32
    float* hw2S = hb1S + 32;             // 384
    float* hb2S = hw2S + 384;            // 16

    int tid = threadIdx.x, lane = tid & 31, w = tid >> 5;
    int rb = blockIdx.x * 64 + w * 8;

    for (int idx = tid; idx < 2048; idx += 256) {
        int i = idx >> 5, l = idx & 31;
        const float* src = (i < 32) ? (wx + i * 128) : (wh + (i - 32) * 128);
        swp[idx * 2]     = packab(src[l], src[32 + l]);
        swp[idx * 2 + 1] = packab(src[64 + l], src[96 + l]);
    }
    for (int i = tid; i < 1024; i += 256) hw1S[i] = hw1[i];
    for (int i = tid; i < 384; i += 256) hw2S[i] = hw2[i];
    if (tid < 32) hb1S[tid] = hb1[tid];
    if (tid < PREDc) hb2S[tid] = hb2[tid];

    u64 bz01 = packab(lb[lane], lb[32 + lane]);
    u64 bz23 = packab(lb[64 + lane], lb[96 + lane]);
    __syncthreads();

    u64* hbw = hb + w * 512;
    const ulonglong2* swp2 = (const ulonglong2*)swp;

    float hcv[8], h[8], c[8];
    #pragma unroll
    for (int r = 0; r < 8; r++) {
        h[r] = 0.f; c[r] = 0.f;
        hcv[r] = g_hc[((size_t)(rb + r) * Tc) * 32 + lane];
    }

    for (int t = 0; t < Tc; t++) {
        #pragma unroll
        for (int r = 0; r < 8; r++) {
            hbw[r * 64 + lane] = pack11(hcv[r]);
            hbw[r * 64 + 32 + lane] = pack11(h[r]);
        }
        float hcn[8];
        if (t + 1 < Tc) {
            #pragma unroll
            for (int r = 0; r < 8; r++)
                hcn[r] = g_hc[((size_t)(rb + r) * Tc + t + 1) * 32 + lane];
        }
        __syncwarp();
        u64 z01[8], z23[8];
        #pragma unroll
        for (int r = 0; r < 8; r++) { z01[r] = bz01; z23[r] = bz23; }
        #pragma unroll 8
        for (int i = 0; i < 64; i += 2) {
            ulonglong2 wA = swp2[i * 32 + lane];
            ulonglong2 wB = swp2[(i + 1) * 32 + lane];
            #pragma unroll
            for (int r = 0; r < 8; r++) {
                ulonglong2 hp = *(const ulonglong2*)&hbw[r * 64 + i];
                ffma2(z01[r], hp.x, wA.x);
                ffma2(z23[r], hp.x, wA.y);
                ffma2(z01[r], hp.y, wB.x);
                ffma2(z23[r], hp.y, wB.y);
            }
        }
        #pragma unroll
        for (int r = 0; r < 8; r++) {
            float2 zif = unpk(z01[r]);
            float2 zgo = unpk(z23[r]);
            float ig = sigmf(zif.x);
            float fg = sigmf(zif.y);
            float gg = tanhf_(zgo.x);
            float og = sigmf(zgo.y);
            c[r] = fg * c[r] + ig * gg;
            h[r] = og * tanhf_(c[r]);
            hcv[r] = hcn[r];
        }
        __syncwarp();
    }

    // head: y = silu(h @ hw1 + hb1) @ hw2 + hb2
    #pragma unroll
    for (int r = 0; r < 8; r++) {
        int row = rb + r;
        int b = row / Nc;
        int n = row % Nc;
        float a = hb1S[lane];
        #pragma unroll 8
        for (int i = 0; i < 32; i++) {
            float hi = __shfl_sync(FULLMASK, h[r], i);
            a += hi * hw1S[i * 32 + lane];
        }
        float y1 = siluf(a);
        float o = (lane < PREDc) ? hb2S[lane] : 0.f;
        #pragma unroll 8
        for (int j = 0; j < 32; j++) {
            float yj = __shfl_sync(FULLMASK, y1, j);
            if (lane < PREDc) o += yj * hw2S[j * PREDc + lane];
        }
        if (lane < Pout) out[((size_t)b * Pout + lane) * Nc + n] = o;
    }
}

// ---------------- launch ----------------
extern "C" void kernel_launch(void* const* d_in, const int* in_sizes, int n_in,
                              void* d_out, int out_size) {
    const float* x       = (const float*)d_in[0];
    const float* xraw    = (const float*)d_in[1];
    const float* W       = (const float*)d_in[3];
    const int*   members = (const int*)d_in[4];
    const int*   centers = (const int*)d_in[5];
    const int*   offsets = (const int*)d_in[6];
    const float* ipw     = (const float*)d_in[7];
    const float* ipb     = (const float*)d_in[8];
    const float* cw      = (const float*)d_in[9];
    const float* cb      = (const float*)d_in[10];
    const float* wx      = (const float*)d_in[11];
    const float* wh      = (const float*)d_in[12];
    const float* lb      = (const float*)d_in[13];
    const float* hw1     = (const float*)d_in[14];
    const float* hb1     = (const float*)d_in[15];
    const float* hw2     = (const float*)d_in[16];
    const float* hb2     = (const float*)d_in[17];
    float* out = (float*)d_out;
    int Pout = out_size / (Bc * Nc);

    int smem_slice = ((Nc + 1) * 32 + 512 + 32) * sizeof(float);          // 130304
    int smem_lstm  = 8192 * sizeof(u64) + 1456 * sizeof(float);           // 71360
    cudaFuncSetAttribute(k_slice, cudaFuncAttributeMaxDynamicSharedMemorySize, smem_slice);
    cudaFuncSetAttribute(k_lstm3, cudaFuncAttributeMaxDynamicSharedMemorySize, smem_lstm);

    k_zero_deg<<<4, 256>>>();
    k_build_edges<<<4, 256>>>(members, centers, offsets);
    k_sort_nodes<<<4, 256>>>();
    k_feat<<<(Bc * Nc * C_RAWc + 255) / 256, 256>>>(xraw);
    k_sim<<<(Bc * Ec + 7) / 8, 256>>>(members, centers, offsets);
    k_wdf<<<Bc + 1, 256>>>(W, ipw, ipb, cw);
    k_slice<<<Bc * Tc, 512, smem_slice>>>(x, cb);
    k_lstm3<<<Bc * Nc / 64, 256, smem_lstm>>>(wx, wh, lb, hw1, hb1, hw2, hb2, out, Pout);
}

// round 10
// speedup vs baseline: 1.5389x; 1.1268x over previous
#include <cuda_runtime.h>
#include <math.h>

#define FULLMASK 0xffffffffu

#define Bc 8
#define Tc 24
#define Nc 1000
#define Ec 1000
#define F_INc 16
#define C_RAWc 8
#define DMc 32
#define HCc 32
#define PREDc 12
#define LAMc 0.3f
#define EPSc 1e-8f
#define MAXD 64
#define ESTRIDE 24     // padded edge member list stride (int4-aligned)

typedef unsigned long long u64;

// ---------------- scratch (device globals; no allocation) ----------------
__device__ int   g_edge_nodes[Ec * ESTRIDE];
__device__ int   g_edge_cnt[Ec];
__device__ int   g_node_edges[Nc * MAXD];
__device__ int   g_node_deg[Nc];
__device__ float g_feat[Bc * Nc * 16];
__device__ float g_msum[Bc * Ec];
__device__ float g_Wd[Bc * Ec];
__device__ float g_dvi[Bc * Nc];
__device__ float g_ipwc[F_INc * DMc];   // folded ipw @ cw
__device__ float g_ipbc[DMc];           // folded ipb @ cw
__device__ float g_hc[(size_t)Bc * Nc * Tc * HCc];   // conv outputs (LSTM inputs)

// ---------------- math helpers ----------------
__device__ __forceinline__ float sigmf(float x) { return __fdividef(1.f, 1.f + __expf(-x)); }
__device__ __forceinline__ float tanhf_(float x) { return 2.f * sigmf(2.f * x) - 1.f; }
__device__ __forceinline__ float siluf(float x) { return x * sigmf(x); }

__device__ __forceinline__ u64 pack11(float x) {
    u64 r; asm("mov.b64 %0, {%1, %1};" : "=l"(r) : "f"(x)); return r;
}
__device__ __forceinline__ u64 packab(float a, float b) {
    u64 r; asm("mov.b64 %0, {%1, %2};" : "=l"(r) : "f"(a), "f"(b)); return r;
}
__device__ __forceinline__ void ffma2(u64& d, u64 a, u64 b) {
    asm("fma.rn.f32x2 %0, %1, %2, %0;" : "+l"(d) : "l"(a), "l"(b));
}
__device__ __forceinline__ float2 unpk(u64 v) {
    float2 f; asm("mov.b64 {%0, %1}, %2;" : "=f"(f.x), "=f"(f.y) : "l"(v)); return f;
}

// ---------------- adjacency build ----------------
__global__ void k_zero_deg() {
    int i = blockIdx.x * blockDim.x + threadIdx.x;
    if (i < Nc) g_node_deg[i] = 0;
}

__global__ void k_build_edges(const int* __restrict__ members,
                              const int* __restrict__ centers,
                              const int* __restrict__ offsets) {
    int e = blockIdx.x * blockDim.x + threadIdx.x;
    if (e >= Ec) return;
    int s = offsets[e], t = offsets[e + 1];
    int list[ESTRIDE];
    int cnt = 0;
    for (int m = s; m < t && cnt < ESTRIDE; m++) {
        int n = members[m];
        bool dup = false;
        for (int k = 0; k < cnt; k++) if (list[k] == n) { dup = true; break; }
        if (!dup) list[cnt++] = n;
    }
    {
        int c = centers[e];
        bool dup = false;
        for (int k = 0; k < cnt; k++) if (list[k] == c) { dup = true; break; }
        if (!dup && cnt < ESTRIDE) list[cnt++] = c;
    }
    g_edge_cnt[e] = cnt;
    for (int k = 0; k < cnt; k++) {
        int n = list[k];
        g_edge_nodes[e * ESTRIDE + k] = n;
        int pos = atomicAdd(&g_node_deg[n], 1);
        if (pos < MAXD) g_node_edges[n * MAXD + pos] = e;
    }
    for (int k = cnt; k < ESTRIDE; k++) g_edge_nodes[e * ESTRIDE + k] = Nc;  // dummy zero row
}

__global__ void k_sort_nodes() {
    int n = blockIdx.x * blockDim.x + threadIdx.x;
    if (n >= Nc) return;
    int d = g_node_deg[n];
    if (d > MAXD) d = MAXD;
    g_node_deg[n] = d;
    int* L = g_node_edges + n * MAXD;
    for (int i = 1; i < d; i++) {
        int key = L[i];
        int j = i - 1;
        while (j >= 0 && L[j] > key) { L[j + 1] = L[j]; j--; }
        L[j + 1] = key;
    }
    int d8 = (d + 7) & ~7;
    if (d8 > MAXD) d8 = MAXD;
    for (int i = d; i < d8; i++) L[i] = Ec;  // dummy: smem row 1000 zeroed
}

// ---------------- dynamic features: mean/std over T ----------------
__global__ void k_feat(const float* __restrict__ xraw) {
    int idx = blockIdx.x * blockDim.x + threadIdx.x;
    if (idx >= Bc * Nc * C_RAWc) return;
    int c = idx % C_RAWc;
    int n = (idx / C_RAWc) % Nc;
    int b = idx / (C_RAWc * Nc);
    float s1 = 0.f, s2 = 0.f;
    #pragma unroll
    for (int t = 0; t < Tc; t++) {
        float v = xraw[((b * Tc + t) * Nc + n) * C_RAWc + c];
        s1 += v; s2 += v * v;
    }
    float mean = s1 * (1.f / Tc);
    float var = s2 * (1.f / Tc) - mean * mean;
    if (var < 0.f) var = 0.f;
    g_feat[(b * Nc + n) * 16 + c] = mean;
    g_feat[(b * Nc + n) * 16 + C_RAWc + c] = sqrtf(var);
}

// ---------------- per-edge mean similarity (warp per (b,e)) ----------------
__global__ void k_sim(const int* __restrict__ members,
                      const int* __restrict__ centers,
                      const int* __restrict__ offsets) {
    int gid = blockIdx.x * (blockDim.x >> 5) + (threadIdx.x >> 5);
    if (gid >= Bc * Ec) return;
    int e = gid % Ec;
    int b = gid / Ec;
    int lane = threadIdx.x & 31;
    int s = offsets[e];
    int cntm = offsets[e + 1] - s;
    int cn = centers[e];
    const float4* cf4 = (const float4*)(g_feat + (b * Nc + cn) * 16);
    float4 c0 = cf4[0], c1 = cf4[1], c2 = cf4[2], c3 = cf4[3];
    float cn2 = c0.x*c0.x + c0.y*c0.y + c0.z*c0.z + c0.w*c0.w
              + c1.x*c1.x + c1.y*c1.y + c1.z*c1.z + c1.w*c1.w
              + c2.x*c2.x + c2.y*c2.y + c2.z*c2.z + c2.w*c2.w
              + c3.x*c3.x + c3.y*c3.y + c3.z*c3.z + c3.w*c3.w;
    float cnorm = sqrtf(cn2);
    float acc = 0.f;
    for (int m = lane; m < cntm; m += 32) {
        int n = members[s + m];
        const float4* mf4 = (const float4*)(g_feat + (b * Nc + n) * 16);
        float4 m0 = mf4[0], m1 = mf4[1], m2 = mf4[2], m3 = mf4[3];
        float dot = m0.x*c0.x + m0.y*c0.y + m0.z*c0.z + m0.w*c0.w
                  + m1.x*c1.x + m1.y*c1.y + m1.z*c1.z + m1.w*c1.w
                  + m2.x*c2.x + m2.y*c2.y + m2.z*c2.z + m2.w*c2.w
                  + m3.x*c3.x + m3.y*c3.y + m3.z*c3.z + m3.w*c3.w;
        float mn2 = m0.x*m0.x + m0.y*m0.y + m0.z*m0.z + m0.w*m0.w
                  + m1.x*m1.x + m1.y*m1.y + m1.z*m1.z + m1.w*m1.w
                  + m2.x*m2.x + m2.y*m2.y + m2.z*m2.z + m2.w*m2.w
                  + m3.x*m3.x + m3.y*m3.y + m3.z*m3.z + m3.w*m3.w;
        float sim = dot / (sqrtf(mn2) * cnorm + EPSc);
        acc += fminf(fmaxf(sim, 0.f), 1.f);
    }
    #pragma unroll
    for (int o = 16; o > 0; o >>= 1) acc += __shfl_xor_sync(FULLMASK, acc, o);
    if (lane == 0) {
        float count = (float)cntm;
        if (count < 1.f) count = 1.f;
        g_msum[b * Ec + e] = acc / count;
    }
}

// ---------------- fused: per-batch Wd (min/max) + dvi; block 8 does the conv fold ----------------
__global__ __launch_bounds__(256) void k_wdf(const float* __restrict__ W,
                                             const float* __restrict__ ipw,
                                             const float* __restrict__ ipb,
                                             const float* __restrict__ cw) {
    __shared__ float sWd[Ec];
    __shared__ float rmn[256], rmx[256];
    int b = blockIdx.x;
    int tid = threadIdx.x;

    if (b < Bc) {
        float mn = 1e30f, mx = -1e30f;
        for (int e = tid; e < Ec; e += 256) {
            float v = g_msum[b * Ec + e];
            mn = fminf(mn, v); mx = fmaxf(mx, v);
        }
        rmn[tid] = mn; rmx[tid] = mx;
        __syncthreads();
        for (int s = 128; s > 0; s >>= 1) {
            if (tid < s) {
                rmn[tid] = fminf(rmn[tid], rmn[tid + s]);
                rmx[tid] = fmaxf(rmx[tid], rmx[tid + s]);
            }
            __syncthreads();
        }
        mn = rmn[0]; mx = rmx[0];
        float inv = __fdividef(1.f, mx - mn + EPSc);
        for (int e = tid; e < Ec; e += 256) {
            float v = (g_msum[b * Ec + e] - mn) * inv;
            float wd = W[e] * (1.f + LAMc * v);
            sWd[e] = wd;
            g_Wd[b * Ec + e] = wd;
        }
        __syncthreads();
        // dvi from smem-resident Wd (lists sorted -> deterministic order)
        for (int n = tid; n < Nc; n += 256) {
            int d = g_node_deg[n];
            const int* L = g_node_edges + n * MAXD;
            float s = 0.f;
            for (int i = 0; i < d; i++) s += sWd[L[i]];
            g_dvi[b * Nc + n] = rsqrtf(fmaxf(s, EPSc));
        }
    } else {
        // fold conv into input projection: ipwc = ipw@cw, ipbc = ipb@cw
        for (int it = tid; it < F_INc * DMc; it += 256) {
            int k = it >> 5, j = it & 31;
            float s = 0.f;
            #pragma unroll
            for (int f = 0; f < DMc; f++) s += ipw[k * DMc + f] * cw[f * HCc + j];
            g_ipwc[it] = s;
        }
        if (tid < 32) {
            float sb = 0.f;
            #pragma unroll
            for (int f = 0; f < DMc; f++) sb += ipb[f] * cw[f * HCc + tid];
            g_ipbc[tid] = sb;
        }
    }
}

// ---------------- half-slice kernel: block per ((b,t), feature-half) ----------------
// 65KB smem -> 2 blocks/SM; warps process 2 edges/nodes per access (half-warp each).
__global__ __launch_bounds__(512) void k_slice2(const float* __restrict__ x,
                                                const float* __restrict__ cbg) {
    extern __shared__ float xs[];          // (Nc+1)*16, reused for edge features
    float* sipw = xs + (Nc + 1) * 16;      // 256: [k*16 + j]
    float* sipb = sipw + 256;              // 16
    int blk = blockIdx.x;
    int bt = blk >> 1;
    int half = blk & 1;
    int b = bt / Tc;
    int t = bt % Tc;
    int tid = threadIdx.x;
    int lane = tid & 31, w = tid >> 5;
    int fl = lane & 15;      // feature lane within half
    int sel = lane >> 4;     // which element of the pair this half-warp handles
    int h16 = half * 16;

    if (tid < 256) {
        int k = tid >> 4, j = tid & 15;
        sipw[tid] = g_ipwc[k * 32 + h16 + j];
    }
    if (tid < 16) sipb[tid] = g_ipbc[h16 + tid];
    __syncthreads();

    // phase 1: ys half = dvi * (x @ ipwc_half + ipbc_half); row 1000 zeroed
    const float* xb = x + (size_t)bt * Nc * F_INc;
    for (int i = tid; i < (Nc + 1) * 4; i += 512) {
        int n = i >> 2, q = (i & 3) * 4;
        float a0 = 0.f, a1 = 0.f, a2 = 0.f, a3 = 0.f;
        if (n < Nc) {
            const float* xr = xb + n * F_INc;
            a0 = sipb[q]; a1 = sipb[q + 1]; a2 = sipb[q + 2]; a3 = sipb[q + 3];
            #pragma unroll
            for (int k = 0; k < F_INc; k++) {
                float xv = xr[k];
                a0 += xv * sipw[k * 16 + q];
                a1 += xv * sipw[k * 16 + q + 1];
                a2 += xv * sipw[k * 16 + q + 2];
                a3 += xv * sipw[k * 16 + q + 3];
            }
            float d = g_dvi[b * Nc + n];
            a0 *= d; a1 *= d; a2 *= d; a3 *= d;
        }
        *(float4*)(xs + n * 16 + q) = make_float4(a0, a1, a2, a3);
    }
    __syncthreads();

    // phase 2: edge gather into registers; warp w handles edges [w*64, w*64+64) as 32 pairs
    int e_base = w * 64;
    float u_reg[32];
    #pragma unroll
    for (int s = 0; s < 32; s++) {
        int e = e_base + 2 * s + sel;
        float uv = 0.f;
        if (e < Ec) {
            const int4* ip = (const int4*)(g_edge_nodes + e * ESTRIDE);
            int4 a0 = ip[0], a1 = ip[1], a2 = ip[2], a3 = ip[3], a4 = ip[4], a5 = ip[5];
            float p0 = xs[a0.x * 16 + fl] + xs[a1.x * 16 + fl]
                     + xs[a2.x * 16 + fl] + xs[a3.x * 16 + fl]
                     + xs[a4.x * 16 + fl] + xs[a5.x * 16 + fl];
            float p1 = xs[a0.y * 16 + fl] + xs[a1.y * 16 + fl]
                     + xs[a2.y * 16 + fl] + xs[a3.y * 16 + fl]
                     + xs[a4.y * 16 + fl] + xs[a5.y * 16 + fl];
            float p2 = xs[a0.z * 16 + fl] + xs[a1.z * 16 + fl]
                     + xs[a2.z * 16 + fl] + xs[a3.z * 16 + fl]
                     + xs[a4.z * 16 + fl] + xs[a5.z * 16 + fl];
            float p3 = xs[a0.w * 16 + fl] + xs[a1.w * 16 + fl]
                     + xs[a2.w * 16 + fl] + xs[a3.w * 16 + fl]
                     + xs[a4.w * 16 + fl] + xs[a5.w * 16 + fl];
            float sc = __fdividef(g_Wd[b * Ec + e], (float)g_edge_cnt[e]);
            uv = ((p0 + p1) + (p2 + p3)) * sc;
        }
        u_reg[s] = uv;
    }
    __syncthreads();   // all reads of ys complete

    // phase 3: overwrite smem with edge features (+ dummy zero row 1000)
    #pragma unroll
    for (int s = 0; s < 32; s++) {
        int e = e_base + 2 * s + sel;
        if (e < Ec) xs[e * 16 + fl] = u_reg[s];
    }
    if (tid < 16) xs[Nc * 16 + tid] = 0.f;
    __syncthreads();

    // phase 4: node gather + silu -> g_hc half; warp handles node pairs
    float cbv = cbg[h16 + fl];
    for (int np = w; np < Nc / 2; np += 16) {
        int n = np * 2 + sel;
        int deg = g_node_deg[n];
        int d8 = (deg + 7) & ~7;
        const int* L = g_node_edges + n * MAXD;
        float p0 = 0.f, p1 = 0.f;
        for (int k = 0; k < d8; k += 8) {
            int4 a = *(const int4*)(L + k);
            int4 b2 = *(const int4*)(L + k + 4);
            p0 += xs[a.x * 16 + fl] + xs[a.z * 16 + fl]
                + xs[b2.x * 16 + fl] + xs[b2.z * 16 + fl];
            p1 += xs[a.y * 16 + fl] + xs[a.w * 16 + fl]
                + xs[b2.y * 16 + fl] + xs[b2.w * 16 + fl];
        }
        float z = (p0 + p1) * g_dvi[b * Nc + n] + cbv;
        g_hc[((size_t)(b * Nc + n) * Tc + t) * 32 + h16 + fl] = siluf(z);
    }
}

// ---------------- LSTM: smem f32x2 weights, 8 rows/warp, 8 warps/block, 125 blocks ----------------
__global__ __launch_bounds__(256) void k_lstm3(
    const float* __restrict__ wx, const float* __restrict__ wh,
    const float* __restrict__ lb,
    const float* __restrict__ hw1, const float* __restrict__ hb1,
    const float* __restrict__ hw2, const float* __restrict__ hb2,
    float* __restrict__ out, int Pout) {
    extern __shared__ __align__(16) char smr[];
    u64*   swp  = (u64*)smr;             // 4096: {w01,w23} pairs, index (i*32+lane)*2
    u64*   hb   = swp + 4096;            // 8 warps * 8 rows * 64 = 4096
    float* hw1S = (float*)(hb + 4096);   // 1024
    float* hb1S = hw1S + 1024;           // 32
    float* hw2S = hb1S + 32;             // 384
    float* hb2S = hw2S + 384;            // 16

    int tid = threadIdx.x, lane = tid & 31, w = tid >> 5;
    int rb = blockIdx.x * 64 + w * 8;

    for (int idx = tid; idx < 2048; idx += 256) {
        int i = idx >> 5, l = idx & 31;
        const float* src = (i < 32) ? (wx + i * 128) : (wh + (i - 32) * 128);
        swp[idx * 2]     = packab(src[l], src[32 + l]);
        swp[idx * 2 + 1] = packab(src[64 + l], src[96 + l]);
    }
    for (int i = tid; i < 1024; i += 256) hw1S[i] = hw1[i];
    for (int i = tid; i < 384; i += 256) hw2S[i] = hw2[i];
    if (tid < 32) hb1S[tid] = hb1[tid];
    if (tid < PREDc) hb2S[tid] = hb2[tid];

    u64 bz01 = packab(lb[lane], lb[32 + lane]);
    u64 bz23 = packab(lb[64 + lane], lb[96 + lane]);
    __syncthreads();

    u64* hbw = hb + w * 512;
    const ulonglong2* swp2 = (const ulonglong2*)swp;

    float hcv[8], h[8], c[8];
    #pragma unroll
    for (int r = 0; r < 8; r++) {
        h[r] = 0.f; c[r] = 0.f;
        hcv[r] = g_hc[((size_t)(rb + r) * Tc) * 32 + lane];
    }

    for (int t = 0; t < Tc; t++) {
        #pragma unroll
        for (int r = 0; r < 8; r++) {
            hbw[r * 64 + lane] = pack11(hcv[r]);
            hbw[r * 64 + 32 + lane] = pack11(h[r]);
        }
        float hcn[8];
        if (t + 1 < Tc) {
            #pragma unroll
            for (int r = 0; r < 8; r++)
                hcn[r] = g_hc[((size_t)(rb + r) * Tc + t + 1) * 32 + lane];
        }
        __syncwarp();
        u64 z01[8], z23[8];
        #pragma unroll
        for (int r = 0; r < 8; r++) { z01[r] = bz01; z23[r] = bz23; }
        #pragma unroll 8
        for (int i = 0; i < 64; i += 2) {
            ulonglong2 wA = swp2[i * 32 + lane];
            ulonglong2 wB = swp2[(i + 1) * 32 + lane];
            #pragma unroll
            for (int r = 0; r < 8; r++) {
                ulonglong2 hp = *(const ulonglong2*)&hbw[r * 64 + i];
                ffma2(z01[r], hp.x, wA.x);
                ffma2(z23[r], hp.x, wA.y);
                ffma2(z01[r], hp.y, wB.x);
                ffma2(z23[r], hp.y, wB.y);
            }
        }
        #pragma unroll
        for (int r = 0; r < 8; r++) {
            float2 zif = unpk(z01[r]);
            float2 zgo = unpk(z23[r]);
            float ig = sigmf(zif.x);
            float fg = sigmf(zif.y);
            float gg = tanhf_(zgo.x);
            float og = sigmf(zgo.y);
            c[r] = fg * c[r] + ig * gg;
            h[r] = og * tanhf_(c[r]);
            hcv[r] = hcn[r];
        }
        __syncwarp();
    }

    // head: y = silu(h @ hw1 + hb1) @ hw2 + hb2
    #pragma unroll
    for (int r = 0; r < 8; r++) {
        int row = rb + r;
        int b = row / Nc;
        int n = row % Nc;
        float a = hb1S[lane];
        #pragma unroll 8
        for (int i = 0; i < 32; i++) {
            float hi = __shfl_sync(FULLMASK, h[r], i);
            a += hi * hw1S[i * 32 + lane];
        }
        float y1 = siluf(a);
        float o = (lane < PREDc) ? hb2S[lane] : 0.f;
        #pragma unroll 8
        for (int j = 0; j < 32; j++) {
            float yj = __shfl_sync(FULLMASK, y1, j);
            if (lane < PREDc) o += yj * hw2S[j * PREDc + lane];
        }
        if (lane < Pout) out[((size_t)b * Pout + lane) * Nc + n] = o;
    }
}

// ---------------- launch ----------------
extern "C" void kernel_launch(void* const* d_in, const int* in_sizes, int n_in,
                              void* d_out, int out_size) {
    const float* x       = (const float*)d_in[0];
    const float* xraw    = (const float*)d_in[1];
    const float* W       = (const float*)d_in[3];
    const int*   members = (const int*)d_in[4];
    const int*   centers = (const int*)d_in[5];
    const int*   offsets = (const int*)d_in[6];
    const float* ipw     = (const float*)d_in[7];
    const float* ipb     = (const float*)d_in[8];
    const float* cw      = (const float*)d_in[9];
    const float* cb      = (const float*)d_in[10];
    const float* wx      = (const float*)d_in[11];
    const float* wh      = (const float*)d_in[12];
    const float* lb      = (const float*)d_in[13];
    const float* hw1     = (const float*)d_in[14];
    const float* hb1     = (const float*)d_in[15];
    const float* hw2     = (const float*)d_in[16];
    const float* hb2     = (const float*)d_in[17];
    float* out = (float*)d_out;
    int Pout = out_size / (Bc * Nc);

    int smem_slice = ((Nc + 1) * 16 + 256 + 16) * sizeof(float);          // 65152
    int smem_lstm  = 8192 * sizeof(u64) + 1456 * sizeof(float);           // 71360
    cudaFuncSetAttribute(k_slice2, cudaFuncAttributeMaxDynamicSharedMemorySize, smem_slice);
    cudaFuncSetAttribute(k_lstm3, cudaFuncAttributeMaxDynamicSharedMemorySize, smem_lstm);

    k_zero_deg<<<4, 256>>>();
    k_build_edges<<<4, 256>>>(members, centers, offsets);
    k_sort_nodes<<<4, 256>>>();
    k_feat<<<(Bc * Nc * C_RAWc + 255) / 256, 256>>>(xraw);
    k_sim<<<(Bc * Ec + 7) / 8, 256>>>(members, centers, offsets);
    k_wdf<<<Bc + 1, 256>>>(W, ipw, ipb, cw);
    k_slice2<<<Bc * Tc * 2, 512, smem_slice>>>(x, cb);
    k_lstm3<<<Bc * Nc / 64, 256, smem_lstm>>>(wx, wh, lb, hw1, hb1, hw2, hb2, out, Pout);
}

// round 11
// speedup vs baseline: 1.6734x; 1.0874x over previous
#include <cuda_runtime.h>
#include <math.h>

#define FULLMASK 0xffffffffu

#define Bc 8
#define Tc 24
#define Nc 1000
#define Ec 1000
#define F_INc 16
#define C_RAWc 8
#define DMc 32
#define HCc 32
#define PREDc 12
#define LAMc 0.3f
#define EPSc 1e-8f
#define MAXD 64
#define ESTRIDE 24     // padded edge member list stride (int4-aligned)

typedef unsigned long long u64;
typedef unsigned int u32;

// ---------------- scratch (device globals; no allocation) ----------------
__device__ int   g_edge_nodes[Ec * ESTRIDE];
__device__ int   g_edge_cnt[Ec];
__device__ int   g_node_edges[Nc * MAXD];
__device__ int   g_node_deg[Nc];
__device__ float g_feat[Bc * Nc * 16];
__device__ float g_msum[Bc * Ec];
__device__ float g_Wd[Bc * Ec];
__device__ float g_dvi[Bc * Nc];
__device__ float g_ipwc[F_INc * DMc];   // folded ipw @ cw
__device__ float g_ipbc[DMc];           // folded ipb @ cw
__device__ float g_hc[(size_t)Bc * Nc * Tc * HCc];   // conv outputs (LSTM inputs)

// ---------------- math helpers ----------------
__device__ __forceinline__ float sigmf(float x) { return __fdividef(1.f, 1.f + __expf(-x)); }
__device__ __forceinline__ float tanhf_(float x) { return 2.f * sigmf(2.f * x) - 1.f; }
__device__ __forceinline__ float siluf(float x) { return x * sigmf(x); }

__device__ __forceinline__ u32 tf32_of(float f) {
    u32 r; asm("cvt.rna.tf32.f32 %0, %1;" : "=r"(r) : "f"(f)); return r;
}
__device__ __forceinline__ void mma_tf32(float c[4], u32 a0, u32 a1, u32 a2, u32 a3,
                                         u32 b0, u32 b1) {
    asm volatile(
        "mma.sync.aligned.m16n8k8.row.col.f32.tf32.tf32.f32 "
        "{%0,%1,%2,%3}, {%4,%5,%6,%7}, {%8,%9}, {%0,%1,%2,%3};"
        : "+f"(c[0]), "+f"(c[1]), "+f"(c[2]), "+f"(c[3])
        : "r"(a0), "r"(a1), "r"(a2), "r"(a3), "r"(b0), "r"(b1));
}

// ---------------- adjacency build ----------------
__global__ void k_zero_deg() {
    int i = blockIdx.x * blockDim.x + threadIdx.x;
    if (i < Nc) g_node_deg[i] = 0;
}

__global__ void k_build_edges(const int* __restrict__ members,
                              const int* __restrict__ centers,
                              const int* __restrict__ offsets) {
    int e = blockIdx.x * blockDim.x + threadIdx.x;
    if (e >= Ec) return;
    int s = offsets[e], t = offsets[e + 1];
    int list[ESTRIDE];
    int cnt = 0;
    for (int m = s; m < t && cnt < ESTRIDE; m++) {
        int n = members[m];
        bool dup = false;
        for (int k = 0; k < cnt; k++) if (list[k] == n) { dup = true; break; }
        if (!dup) list[cnt++] = n;
    }
    {
        int c = centers[e];
        bool dup = false;
        for (int k = 0; k < cnt; k++) if (list[k] == c) { dup = true; break; }
        if (!dup && cnt < ESTRIDE) list[cnt++] = c;
    }
    g_edge_cnt[e] = cnt;
    for (int k = 0; k < cnt; k++) {
        int n = list[k];
        g_edge_nodes[e * ESTRIDE + k] = n;
        int pos = atomicAdd(&g_node_deg[n], 1);
        if (pos < MAXD) g_node_edges[n * MAXD + pos] = e;
    }
    for (int k = cnt; k < ESTRIDE; k++) g_edge_nodes[e * ESTRIDE + k] = Nc;  // dummy zero row
}

__global__ void k_sort_nodes() {
    int n = blockIdx.x * blockDim.x + threadIdx.x;
    if (n >= Nc) return;
    int d = g_node_deg[n];
    if (d > MAXD) d = MAXD;
    g_node_deg[n] = d;
    int* L = g_node_edges + n * MAXD;
    for (int i = 1; i < d; i++) {
        int key = L[i];
        int j = i - 1;
        while (j >= 0 && L[j] > key) { L[j + 1] = L[j]; j--; }
        L[j + 1] = key;
    }
    int d8 = (d + 7) & ~7;
    if (d8 > MAXD) d8 = MAXD;
    for (int i = d; i < d8; i++) L[i] = Ec;  // dummy: smem row 1000 zeroed
}

// ---------------- dynamic features: mean/std over T ----------------
__global__ void k_feat(const float* __restrict__ xraw) {
    int idx = blockIdx.x * blockDim.x + threadIdx.x;
    if (idx >= Bc * Nc * C_RAWc) return;
    int c = idx % C_RAWc;
    int n = (idx / C_RAWc) % Nc;
    int b = idx / (C_RAWc * Nc);
    float s1 = 0.f, s2 = 0.f;
    #pragma unroll
    for (int t = 0; t < Tc; t++) {
        float v = xraw[((b * Tc + t) * Nc + n) * C_RAWc + c];
        s1 += v; s2 += v * v;
    }
    float mean = s1 * (1.f / Tc);
    float var = s2 * (1.f / Tc) - mean * mean;
    if (var < 0.f) var = 0.f;
    g_feat[(b * Nc + n) * 16 + c] = mean;
    g_feat[(b * Nc + n) * 16 + C_RAWc + c] = sqrtf(var);
}

// ---------------- per-edge mean similarity (warp per (b,e)) ----------------
__global__ void k_sim(const int* __restrict__ members,
                      const int* __restrict__ centers,
                      const int* __restrict__ offsets) {
    int gid = blockIdx.x * (blockDim.x >> 5) + (threadIdx.x >> 5);
    if (gid >= Bc * Ec) return;
    int e = gid % Ec;
    int b = gid / Ec;
    int lane = threadIdx.x & 31;
    int s = offsets[e];
    int cntm = offsets[e + 1] - s;
    int cn = centers[e];
    const float4* cf4 = (const float4*)(g_feat + (b * Nc + cn) * 16);
    float4 c0 = cf4[0], c1 = cf4[1], c2 = cf4[2], c3 = cf4[3];
    float cn2 = c0.x*c0.x + c0.y*c0.y + c0.z*c0.z + c0.w*c0.w
              + c1.x*c1.x + c1.y*c1.y + c1.z*c1.z + c1.w*c1.w
              + c2.x*c2.x + c2.y*c2.y + c2.z*c2.z + c2.w*c2.w
              + c3.x*c3.x + c3.y*c3.y + c3.z*c3.z + c3.w*c3.w;
    float cnorm = sqrtf(cn2);
    float acc = 0.f;
    for (int m = lane; m < cntm; m += 32) {
        int n = members[s + m];
        const float4* mf4 = (const float4*)(g_feat + (b * Nc + n) * 16);
        float4 m0 = mf4[0], m1 = mf4[1], m2 = mf4[2], m3 = mf4[3];
        float dot = m0.x*c0.x + m0.y*c0.y + m0.z*c0.z + m0.w*c0.w
                  + m1.x*c1.x + m1.y*c1.y + m1.z*c1.z + m1.w*c1.w
                  + m2.x*c2.x + m2.y*c2.y + m2.z*c2.z + m2.w*c2.w
                  + m3.x*c3.x + m3.y*c3.y + m3.z*c3.z + m3.w*c3.w;
        float mn2 = m0.x*m0.x + m0.y*m0.y + m0.z*m0.z + m0.w*m0.w
                  + m1.x*m1.x + m1.y*m1.y + m1.z*m1.z + m1.w*m1.w
                  + m2.x*m2.x + m2.y*m2.y + m2.z*m2.z + m2.w*m2.w
                  + m3.x*m3.x + m3.y*m3.y + m3.z*m3.z + m3.w*m3.w;
        float sim = dot / (sqrtf(mn2) * cnorm + EPSc);
        acc += fminf(fmaxf(sim, 0.f), 1.f);
    }
    #pragma unroll
    for (int o = 16; o > 0; o >>= 1) acc += __shfl_xor_sync(FULLMASK, acc, o);
    if (lane == 0) {
        float count = (float)cntm;
        if (count < 1.f) count = 1.f;
        g_msum[b * Ec + e] = acc / count;
    }
}

// ---------------- fused: per-batch Wd (min/max) + dvi; block 8 does the conv fold ----------------
__global__ __launch_bounds__(256) void k_wdf(const float* __restrict__ W,
                                             const float* __restrict__ ipw,
                                             const float* __restrict__ ipb,
                                             const float* __restrict__ cw) {
    __shared__ float sWd[Ec];
    __shared__ float rmn[256], rmx[256];
    int b = blockIdx.x;
    int tid = threadIdx.x;

    if (b < Bc) {
        float mn = 1e30f, mx = -1e30f;
        for (int e = tid; e < Ec; e += 256) {
            float v = g_msum[b * Ec + e];
            mn = fminf(mn, v); mx = fmaxf(mx, v);
        }
        rmn[tid] = mn; rmx[tid] = mx;
        __syncthreads();
        for (int s = 128; s > 0; s >>= 1) {
            if (tid < s) {
                rmn[tid] = fminf(rmn[tid], rmn[tid + s]);
                rmx[tid] = fmaxf(rmx[tid], rmx[tid + s]);
            }
            __syncthreads();
        }
        mn = rmn[0]; mx = rmx[0];
        float inv = __fdividef(1.f, mx - mn + EPSc);
        for (int e = tid; e < Ec; e += 256) {
            float v = (g_msum[b * Ec + e] - mn) * inv;
            float wd = W[e] * (1.f + LAMc * v);
            sWd[e] = wd;
            g_Wd[b * Ec + e] = wd;
        }
        __syncthreads();
        for (int n = tid; n < Nc; n += 256) {
            int d = g_node_deg[n];
            const int* L = g_node_edges + n * MAXD;
            float s = 0.f;
            for (int i = 0; i < d; i++) s += sWd[L[i]];
            g_dvi[b * Nc + n] = rsqrtf(fmaxf(s, EPSc));
        }
    } else {
        for (int it = tid; it < F_INc * DMc; it += 256) {
            int k = it >> 5, j = it & 31;
            float s = 0.f;
            #pragma unroll
            for (int f = 0; f < DMc; f++) s += ipw[k * DMc + f] * cw[f * HCc + j];
            g_ipwc[it] = s;
        }
        if (tid < 32) {
            float sb = 0.f;
            #pragma unroll
            for (int f = 0; f < DMc; f++) sb += ipb[f] * cw[f * HCc + tid];
            g_ipbc[tid] = sb;
        }
    }
}

// ---------------- half-slice kernel: block per ((b,t), feature-half) ----------------
__global__ __launch_bounds__(512) void k_slice2(const float* __restrict__ x,
                                                const float* __restrict__ cbg) {
    extern __shared__ float xs[];          // (Nc+1)*16, reused for edge features
    float* sipw = xs + (Nc + 1) * 16;      // 256: [k*16 + j]
    float* sipb = sipw + 256;              // 16
    int blk = blockIdx.x;
    int bt = blk >> 1;
    int half = blk & 1;
    int b = bt / Tc;
    int t = bt % Tc;
    int tid = threadIdx.x;
    int lane = tid & 31, w = tid >> 5;
    int fl = lane & 15;
    int sel = lane >> 4;
    int h16 = half * 16;

    if (tid < 256) {
        int k = tid >> 4, j = tid & 15;
        sipw[tid] = g_ipwc[k * 32 + h16 + j];
    }
    if (tid < 16) sipb[tid] = g_ipbc[h16 + tid];
    __syncthreads();

    const float* xb = x + (size_t)bt * Nc * F_INc;
    for (int i = tid; i < (Nc + 1) * 4; i += 512) {
        int n = i >> 2, q = (i & 3) * 4;
        float a0 = 0.f, a1 = 0.f, a2 = 0.f, a3 = 0.f;
        if (n < Nc) {
            const float* xr = xb + n * F_INc;
            a0 = sipb[q]; a1 = sipb[q + 1]; a2 = sipb[q + 2]; a3 = sipb[q + 3];
            #pragma unroll
            for (int k = 0; k < F_INc; k++) {
                float xv = xr[k];
                a0 += xv * sipw[k * 16 + q];
                a1 += xv * sipw[k * 16 + q + 1];
                a2 += xv * sipw[k * 16 + q + 2];
                a3 += xv * sipw[k * 16 + q + 3];
            }
            float d = g_dvi[b * Nc + n];
            a0 *= d; a1 *= d; a2 *= d; a3 *= d;
        }
        *(float4*)(xs + n * 16 + q) = make_float4(a0, a1, a2, a3);
    }
    __syncthreads();

    int e_base = w * 64;
    float u_reg[32];
    #pragma unroll
    for (int s = 0; s < 32; s++) {
        int e = e_base + 2 * s + sel;
        float uv = 0.f;
        if (e < Ec) {
            const int4* ip = (const int4*)(g_edge_nodes + e * ESTRIDE);
            int4 a0 = ip[0], a1 = ip[1], a2 = ip[2], a3 = ip[3], a4 = ip[4], a5 = ip[5];
            float p0 = xs[a0.x * 16 + fl] + xs[a1.x * 16 + fl]
                     + xs[a2.x * 16 + fl] + xs[a3.x * 16 + fl]
                     + xs[a4.x * 16 + fl] + xs[a5.x * 16 + fl];
            float p1 = xs[a0.y * 16 + fl] + xs[a1.y * 16 + fl]
                     + xs[a2.y * 16 + fl] + xs[a3.y * 16 + fl]
                     + xs[a4.y * 16 + fl] + xs[a5.y * 16 + fl];
            float p2 = xs[a0.z * 16 + fl] + xs[a1.z * 16 + fl]
                     + xs[a2.z * 16 + fl] + xs[a3.z * 16 + fl]
                     + xs[a4.z * 16 + fl] + xs[a5.z * 16 + fl];
            float p3 = xs[a0.w * 16 + fl] + xs[a1.w * 16 + fl]
                     + xs[a2.w * 16 + fl] + xs[a3.w * 16 + fl]
                     + xs[a4.w * 16 + fl] + xs[a5.w * 16 + fl];
            float sc = __fdividef(g_Wd[b * Ec + e], (float)g_edge_cnt[e]);
            uv = ((p0 + p1) + (p2 + p3)) * sc;
        }
        u_reg[s] = uv;
    }
    __syncthreads();

    #pragma unroll
    for (int s = 0; s < 32; s++) {
        int e = e_base + 2 * s + sel;
        if (e < Ec) xs[e * 16 + fl] = u_reg[s];
    }
    if (tid < 16) xs[Nc * 16 + tid] = 0.f;
    __syncthreads();

    float cbv = cbg[h16 + fl];
    for (int np = w; np < Nc / 2; np += 16) {
        int n = np * 2 + sel;
        int deg = g_node_deg[n];
        int d8 = (deg + 7) & ~7;
        const int* L = g_node_edges + n * MAXD;
        float p0 = 0.f, p1 = 0.f;
        for (int k = 0; k < d8; k += 8) {
            int4 a = *(const int4*)(L + k);
            int4 b2 = *(const int4*)(L + k + 4);
            p0 += xs[a.x * 16 + fl] + xs[a.z * 16 + fl]
                + xs[b2.x * 16 + fl] + xs[b2.z * 16 + fl];
            p1 += xs[a.y * 16 + fl] + xs[a.w * 16 + fl]
                + xs[b2.y * 16 + fl] + xs[b2.w * 16 + fl];
        }
        float z = (p0 + p1) * g_dvi[b * Nc + n] + cbv;
        g_hc[((size_t)(b * Nc + n) * Tc + t) * 32 + h16 + fl] = siluf(z);
    }
}

// ---------------- LSTM: tensor-core recurrence (tf32 2-pass split) ----------------
// block = 64 rows, 8 warps. Warp (g=w&3, mh=w>>2): gate-block g cols [g*32,g*32+32),
// rows [mh*32, mh*32+32). Weights stationary in registers. State: warp w owns rows
// [w*8, w*8+8), lane = hidden index. sA = [hc | h] split hi/lo, stride 68 (conflict-free).
#define ASTR 68
#define ZSTR 132
__global__ __launch_bounds__(256) void k_lstm_tc(
    const float* __restrict__ wx, const float* __restrict__ wh,
    const float* __restrict__ lb,
    const float* __restrict__ hw1, const float* __restrict__ hb1,
    const float* __restrict__ hw2, const float* __restrict__ hb2,
    float* __restrict__ out, int Pout) {
    extern __shared__ __align__(16) float sm[];
    float* sAhi = sm;                    // 64*68 = 4352
    float* sAlo = sAhi + 64 * ASTR;      // 4352
    float* zbuf = sAlo + 64 * ASTR;      // 64*132 = 8448
    float* lbS  = zbuf + 64 * ZSTR;      // 128
    float* hw1S = lbS + 128;             // 1024
    float* hb1S = hw1S + 1024;           // 32
    float* hw2S = hb1S + 32;             // 384
    float* hb2S = hw2S + 384;            // 16

    int tid = threadIdx.x;
    int lane = tid & 31, w = tid >> 5;
    int gid = lane >> 2, tig = lane & 3;
    int gblk = w & 3, mh = w >> 2;
    int rb = blockIdx.x * 64;

    // stage head weights + biases
    for (int i = tid; i < 1024; i += 256) hw1S[i] = hw1[i];
    for (int i = tid; i < 384; i += 256) hw2S[i] = hw2[i];
    if (tid < 128) lbS[tid] = lb[tid];
    if (tid < 32) hb1S[tid] = hb1[tid];
    if (tid < PREDc) hb2S[tid] = hb2[tid];

    // stationary weights: B[k][n] = [wx;wh], warp's slice cols [gblk*32, +32)
    u32 bw0[8][4], bw1[8][4];
    #pragma unroll
    for (int ks = 0; ks < 8; ks++) {
        #pragma unroll
        for (int nt = 0; nt < 4; nt++) {
            int col = gblk * 32 + nt * 8 + gid;
            int k0 = ks * 8 + tig;
            int k1 = k0 + 4;
            float f0 = (k0 < 32) ? wx[k0 * 128 + col] : wh[(k0 - 32) * 128 + col];
            float f1 = (k1 < 32) ? wx[k1 * 128 + col] : wh[(k1 - 32) * 128 + col];
            bw0[ks][nt] = tf32_of(f0);
            bw1[ks][nt] = tf32_of(f1);
        }
    }

    // init state + fill sA for t=0 (warp owns rows [w*8, w*8+8), lane = hidden idx)
    int r0 = w * 8;
    float h[8], cst[8];
    #pragma unroll
    for (int q = 0; q < 8; q++) {
        h[q] = 0.f; cst[q] = 0.f;
        int r = r0 + q;
        float hc = g_hc[((size_t)(rb + r) * Tc) * 32 + lane];
        u32 hib = tf32_of(hc);
        float hif = __uint_as_float(hib);
        sAhi[r * ASTR + lane] = hif;
        sAlo[r * ASTR + lane] = hc - hif;
        sAhi[r * ASTR + 32 + lane] = 0.f;
        sAlo[r * ASTR + 32 + lane] = 0.f;
    }
    __syncthreads();

    for (int t = 0; t < Tc; t++) {
        // prefetch hc(t+1) for owned rows (hidden under mma phase)
        float hcn[8];
        if (t + 1 < Tc) {
            #pragma unroll
            for (int q = 0; q < 8; q++)
                hcn[q] = g_hc[((size_t)(rb + r0 + q) * Tc + t + 1) * 32 + lane];
        }

        // mma phase: z = [hc;h] @ W + lb  (2-pass hi/lo split)
        float cc[2][4][4];
        #pragma unroll
        for (int mt = 0; mt < 2; mt++) {
            #pragma unroll
            for (int nt = 0; nt < 4; nt++) {
                int col = gblk * 32 + nt * 8 + tig * 2;
                cc[mt][nt][0] = lbS[col];
                cc[mt][nt][1] = lbS[col + 1];
                cc[mt][nt][2] = lbS[col];
                cc[mt][nt][3] = lbS[col + 1];
            }
        }
        #pragma unroll
        for (int ks = 0; ks < 8; ks++) {
            #pragma unroll
            for (int mt = 0; mt < 2; mt++) {
                int row = (mh * 2 + mt) * 16 + gid;
                int ca = ks * 8 + tig;
                u32 a0h = __float_as_uint(sAhi[row * ASTR + ca]);
                u32 a1h = __float_as_uint(sAhi[(row + 8) * ASTR + ca]);
                u32 a2h = __float_as_uint(sAhi[row * ASTR + ca + 4]);
                u32 a3h = __float_as_uint(sAhi[(row + 8) * ASTR + ca + 4]);
                u32 a0l = __float_as_uint(sAlo[row * ASTR + ca]);
                u32 a1l = __float_as_uint(sAlo[(row + 8) * ASTR + ca]);
                u32 a2l = __float_as_uint(sAlo[row * ASTR + ca + 4]);
                u32 a3l = __float_as_uint(sAlo[(row + 8) * ASTR + ca + 4]);
                #pragma unroll
                for (int nt = 0; nt < 4; nt++) {
                    mma_tf32(cc[mt][nt], a0h, a1h, a2h, a3h, bw0[ks][nt], bw1[ks][nt]);
                    mma_tf32(cc[mt][nt], a0l, a1l, a2l, a3l, bw0[ks][nt], bw1[ks][nt]);
                }
            }
        }
        // store z to zbuf
        #pragma unroll
        for (int mt = 0; mt < 2; mt++) {
            int row = (mh * 2 + mt) * 16 + gid;
            #pragma unroll
            for (int nt = 0; nt < 4; nt++) {
                int col = gblk * 32 + nt * 8 + tig * 2;
                *(float2*)&zbuf[row * ZSTR + col] = make_float2(cc[mt][nt][0], cc[mt][nt][1]);
                *(float2*)&zbuf[(row + 8) * ZSTR + col] = make_float2(cc[mt][nt][2], cc[mt][nt][3]);
            }
        }
        __syncthreads();

        // state phase: owned rows
        #pragma unroll
        for (int q = 0; q < 8; q++) {
            int r = r0 + q;
            float zi = zbuf[r * ZSTR + lane];
            float zf = zbuf[r * ZSTR + 32 + lane];
            float zg = zbuf[r * ZSTR + 64 + lane];
            float zo = zbuf[r * ZSTR + 96 + lane];
            float ig = sigmf(zi);
            float fg = sigmf(zf);
            float gg = tanhf_(zg);
            float og = sigmf(zo);
            cst[q] = fg * cst[q] + ig * gg;
            h[q] = og * tanhf_(cst[q]);
            u32 hib = tf32_of(h[q]);
            float hif = __uint_as_float(hib);
            sAhi[r * ASTR + 32 + lane] = hif;
            sAlo[r * ASTR + 32 + lane] = h[q] - hif;
            if (t + 1 < Tc) {
                float hc = hcn[q];
                u32 cb2 = tf32_of(hc);
                float cf2 = __uint_as_float(cb2);
                sAhi[r * ASTR + lane] = cf2;
                sAlo[r * ASTR + lane] = hc - cf2;
            }
        }
        __syncthreads();
    }

    // head: y = silu(h @ hw1 + hb1) @ hw2 + hb2   (warp owns rows r0..r0+8)
    #pragma unroll
    for (int q = 0; q < 8; q++) {
        int row = rb + r0 + q;
        int b = row / Nc;
        int n = row % Nc;
        float a = hb1S[lane];
        #pragma unroll 8
        for (int i = 0; i < 32; i++) {
            float hi = __shfl_sync(FULLMASK, h[q], i);
            a += hi * hw1S[i * 32 + lane];
        }
        float y1 = siluf(a);
        float o = (lane < PREDc) ? hb2S[lane] : 0.f;
        #pragma unroll 8
        for (int j = 0; j < 32; j++) {
            float yj = __shfl_sync(FULLMASK, y1, j);
            if (lane < PREDc) o += yj * hw2S[j * PREDc + lane];
        }
        if (lane < Pout) out[((size_t)b * Pout + lane) * Nc + n] = o;
    }
}

// ---------------- launch ----------------
extern "C" void kernel_launch(void* const* d_in, const int* in_sizes, int n_in,
                              void* d_out, int out_size) {
    const float* x       = (const float*)d_in[0];
    const float* xraw    = (const float*)d_in[1];
    const float* W       = (const float*)d_in[3];
    const int*   members = (const int*)d_in[4];
    const int*   centers = (const int*)d_in[5];
    const int*   offsets = (const int*)d_in[6];
    const float* ipw     = (const float*)d_in[7];
    const float* ipb     = (const float*)d_in[8];
    const float* cw      = (const float*)d_in[9];
    const float* cb      = (const float*)d_in[10];
    const float* wx      = (const float*)d_in[11];
    const float* wh      = (const float*)d_in[12];
    const float* lb      = (const float*)d_in[13];
    const float* hw1     = (const float*)d_in[14];
    const float* hb1     = (const float*)d_in[15];
    const float* hw2     = (const float*)d_in[16];
    const float* hb2     = (const float*)d_in[17];
    float* out = (float*)d_out;
    int Pout = out_size / (Bc * Nc);

    int smem_slice = ((Nc + 1) * 16 + 256 + 16) * sizeof(float);                       // 65152
    int smem_lstm  = (64 * ASTR * 2 + 64 * ZSTR + 128 + 1024 + 32 + 384 + 16) * 4;     // ~75KB
    cudaFuncSetAttribute(k_slice2, cudaFuncAttributeMaxDynamicSharedMemorySize, smem_slice);
    cudaFuncSetAttribute(k_lstm_tc, cudaFuncAttributeMaxDynamicSharedMemorySize, smem_lstm);

    k_zero_deg<<<4, 256>>>();
    k_build_edges<<<4, 256>>>(members, centers, offsets);
    k_sort_nodes<<<4, 256>>>();
    k_feat<<<(Bc * Nc * C_RAWc + 255) / 256, 256>>>(xraw);
    k_sim<<<(Bc * Ec + 7) / 8, 256>>>(members, centers, offsets);
    k_wdf<<<Bc + 1, 256>>>(W, ipw, ipb, cw);
    k_slice2<<<Bc * Tc * 2, 512, smem_slice>>>(x, cb);
    k_lstm_tc<<<Bc * Nc / 64, 256, smem_lstm>>>(wx, wh, lb, hw1, hb1, hw2, hb2, out, Pout);
}

// round 12
// speedup vs baseline: 1.7430x; 1.0416x over previous
#include <cuda_runtime.h>
#include <math.h>

#define FULLMASK 0xffffffffu

#define Bc 8
#define Tc 24
#define Nc 1000
#define Ec 1000
#define F_INc 16
#define C_RAWc 8
#define DMc 32
#define HCc 32
#define PREDc 12
#define LAMc 0.3f
#define EPSc 1e-8f
#define MAXD 64
#define ESTRIDE 24     // padded edge member list stride (int4-aligned)

typedef unsigned long long u64;
typedef unsigned int u32;

// ---------------- scratch (device globals; no allocation) ----------------
__device__ int   g_edge_nodes[Ec * ESTRIDE];
__device__ int   g_edge_cnt[Ec];
__device__ int   g_node_edges[Nc * MAXD];
__device__ int   g_node_deg[Nc];
__device__ float g_feat[Bc * Nc * 16];
__device__ float g_msum[Bc * Ec];
__device__ float g_Wd[Bc * Ec];
__device__ float g_dvi[Bc * Nc];
__device__ float g_ipwc[F_INc * DMc];   // folded ipw @ cw
__device__ float g_ipbc[DMc];           // folded ipb @ cw
__device__ float g_hc[(size_t)Bc * Nc * Tc * HCc];   // conv outputs (LSTM inputs)

// ---------------- math helpers ----------------
__device__ __forceinline__ float sigmf(float x) { return __fdividef(1.f, 1.f + __expf(-x)); }
__device__ __forceinline__ float tanhf_(float x) { return 2.f * sigmf(2.f * x) - 1.f; }
__device__ __forceinline__ float siluf(float x) { return x * sigmf(x); }

__device__ __forceinline__ u32 tf32_of(float f) {
    u32 r; asm("cvt.rna.tf32.f32 %0, %1;" : "=r"(r) : "f"(f)); return r;
}
__device__ __forceinline__ void mma_tf32(float c[4], u32 a0, u32 a1, u32 a2, u32 a3,
                                         u32 b0, u32 b1) {
    asm volatile(
        "mma.sync.aligned.m16n8k8.row.col.f32.tf32.tf32.f32 "
        "{%0,%1,%2,%3}, {%4,%5,%6,%7}, {%8,%9}, {%0,%1,%2,%3};"
        : "+f"(c[0]), "+f"(c[1]), "+f"(c[2]), "+f"(c[3])
        : "r"(a0), "r"(a1), "r"(a2), "r"(a3), "r"(b0), "r"(b1));
}

// ---------------- K1: dynamic features (blocks 0..249) + zero node degs (blocks 250..253) ----------------
__global__ void k_feat_zero(const float* __restrict__ xraw) {
    if (blockIdx.x >= 250) {
        int i = (blockIdx.x - 250) * blockDim.x + threadIdx.x;
        if (i < Nc) g_node_deg[i] = 0;
        return;
    }
    int idx = blockIdx.x * blockDim.x + threadIdx.x;
    if (idx >= Bc * Nc * C_RAWc) return;
    int c = idx % C_RAWc;
    int n = (idx / C_RAWc) % Nc;
    int b = idx / (C_RAWc * Nc);
    float s1 = 0.f, s2 = 0.f;
    #pragma unroll
    for (int t = 0; t < Tc; t++) {
        float v = xraw[((b * Tc + t) * Nc + n) * C_RAWc + c];
        s1 += v; s2 += v * v;
    }
    float mean = s1 * (1.f / Tc);
    float var = s2 * (1.f / Tc) - mean * mean;
    if (var < 0.f) var = 0.f;
    g_feat[(b * Nc + n) * 16 + c] = mean;
    g_feat[(b * Nc + n) * 16 + C_RAWc + c] = sqrtf(var);
}

// ---------------- K2: per-edge similarity (blocks 0..999) + edge-list build (1000..1003) ----------------
__global__ void k_sim_build(const int* __restrict__ members,
                            const int* __restrict__ centers,
                            const int* __restrict__ offsets) {
    if (blockIdx.x >= 1000) {
        // build edge node lists + node degrees
        int e = (blockIdx.x - 1000) * blockDim.x + threadIdx.x;
        if (e >= Ec) return;
        int s = offsets[e], t = offsets[e + 1];
        int list[ESTRIDE];
        int cnt = 0;
        for (int m = s; m < t && cnt < ESTRIDE; m++) {
            int n = members[m];
            bool dup = false;
            for (int k = 0; k < cnt; k++) if (list[k] == n) { dup = true; break; }
            if (!dup) list[cnt++] = n;
        }
        {
            int c = centers[e];
            bool dup = false;
            for (int k = 0; k < cnt; k++) if (list[k] == c) { dup = true; break; }
            if (!dup && cnt < ESTRIDE) list[cnt++] = c;
        }
        g_edge_cnt[e] = cnt;
        for (int k = 0; k < cnt; k++) {
            int n = list[k];
            g_edge_nodes[e * ESTRIDE + k] = n;
            int pos = atomicAdd(&g_node_deg[n], 1);
            if (pos < MAXD) g_node_edges[n * MAXD + pos] = e;
        }
        for (int k = cnt; k < ESTRIDE; k++) g_edge_nodes[e * ESTRIDE + k] = Nc;
        return;
    }
    int gid = blockIdx.x * (blockDim.x >> 5) + (threadIdx.x >> 5);
    if (gid >= Bc * Ec) return;
    int e = gid % Ec;
    int b = gid / Ec;
    int lane = threadIdx.x & 31;
    int s = offsets[e];
    int cntm = offsets[e + 1] - s;
    int cn = centers[e];
    const float4* cf4 = (const float4*)(g_feat + (b * Nc + cn) * 16);
    float4 c0 = cf4[0], c1 = cf4[1], c2 = cf4[2], c3 = cf4[3];
    float cn2 = c0.x*c0.x + c0.y*c0.y + c0.z*c0.z + c0.w*c0.w
              + c1.x*c1.x + c1.y*c1.y + c1.z*c1.z + c1.w*c1.w
              + c2.x*c2.x + c2.y*c2.y + c2.z*c2.z + c2.w*c2.w
              + c3.x*c3.x + c3.y*c3.y + c3.z*c3.z + c3.w*c3.w;
    float cnorm = sqrtf(cn2);
    float acc = 0.f;
    for (int m = lane; m < cntm; m += 32) {
        int n = members[s + m];
        const float4* mf4 = (const float4*)(g_feat + (b * Nc + n) * 16);
        float4 m0 = mf4[0], m1 = mf4[1], m2 = mf4[2], m3 = mf4[3];
        float dot = m0.x*c0.x + m0.y*c0.y + m0.z*c0.z + m0.w*c0.w
                  + m1.x*c1.x + m1.y*c1.y + m1.z*c1.z + m1.w*c1.w
                  + m2.x*c2.x + m2.y*c2.y + m2.z*c2.z + m2.w*c2.w
                  + m3.x*c3.x + m3.y*c3.y + m3.z*c3.z + m3.w*c3.w;
        float mn2 = m0.x*m0.x + m0.y*m0.y + m0.z*m0.z + m0.w*m0.w
                  + m1.x*m1.x + m1.y*m1.y + m1.z*m1.z + m1.w*m1.w
                  + m2.x*m2.x + m2.y*m2.y + m2.z*m2.z + m2.w*m2.w
                  + m3.x*m3.x + m3.y*m3.y + m3.z*m3.z + m3.w*m3.w;
        float sim = dot / (sqrtf(mn2) * cnorm + EPSc);
        acc += fminf(fmaxf(sim, 0.f), 1.f);
    }
    #pragma unroll
    for (int o = 16; o > 0; o >>= 1) acc += __shfl_xor_sync(FULLMASK, acc, o);
    if (lane == 0) {
        float count = (float)cntm;
        if (count < 1.f) count = 1.f;
        g_msum[b * Ec + e] = acc / count;
    }
}

// ---------------- sort node edge lists (deterministic gather order) ----------------
__global__ void k_sort_nodes() {
    int n = blockIdx.x * blockDim.x + threadIdx.x;
    if (n >= Nc) return;
    int d = g_node_deg[n];
    if (d > MAXD) d = MAXD;
    g_node_deg[n] = d;
    int* L = g_node_edges + n * MAXD;
    for (int i = 1; i < d; i++) {
        int key = L[i];
        int j = i - 1;
        while (j >= 0 && L[j] > key) { L[j + 1] = L[j]; j--; }
        L[j + 1] = key;
    }
    int d8 = (d + 7) & ~7;
    if (d8 > MAXD) d8 = MAXD;
    for (int i = d; i < d8; i++) L[i] = Ec;  // dummy: smem row 1000 zeroed
}

// ---------------- fused: per-batch Wd (min/max) + dvi; block 8 does the conv fold ----------------
__global__ __launch_bounds__(256) void k_wdf(const float* __restrict__ W,
                                             const float* __restrict__ ipw,
                                             const float* __restrict__ ipb,
                                             const float* __restrict__ cw) {
    __shared__ float sWd[Ec];
    __shared__ float rmn[256], rmx[256];
    int b = blockIdx.x;
    int tid = threadIdx.x;

    if (b < Bc) {
        float mn = 1e30f, mx = -1e30f;
        for (int e = tid; e < Ec; e += 256) {
            float v = g_msum[b * Ec + e];
            mn = fminf(mn, v); mx = fmaxf(mx, v);
        }
        rmn[tid] = mn; rmx[tid] = mx;
        __syncthreads();
        for (int s = 128; s > 0; s >>= 1) {
            if (tid < s) {
                rmn[tid] = fminf(rmn[tid], rmn[tid + s]);
                rmx[tid] = fmaxf(rmx[tid], rmx[tid + s]);
            }
            __syncthreads();
        }
        mn = rmn[0]; mx = rmx[0];
        float inv = __fdividef(1.f, mx - mn + EPSc);
        for (int e = tid; e < Ec; e += 256) {
            float v = (g_msum[b * Ec + e] - mn) * inv;
            float wd = W[e] * (1.f + LAMc * v);
            sWd[e] = wd;
            g_Wd[b * Ec + e] = wd;
        }
        __syncthreads();
        for (int n = tid; n < Nc; n += 256) {
            int d = g_node_deg[n];
            const int* L = g_node_edges + n * MAXD;
            float s = 0.f;
            for (int i = 0; i < d; i++) s += sWd[L[i]];
            g_dvi[b * Nc + n] = rsqrtf(fmaxf(s, EPSc));
        }
    } else {
        for (int it = tid; it < F_INc * DMc; it += 256) {
            int k = it >> 5, j = it & 31;
            float s = 0.f;
            #pragma unroll
            for (int f = 0; f < DMc; f++) s += ipw[k * DMc + f] * cw[f * HCc + j];
            g_ipwc[it] = s;
        }
        if (tid < 32) {
            float sb = 0.f;
            #pragma unroll
            for (int f = 0; f < DMc; f++) sb += ipb[f] * cw[f * HCc + tid];
            g_ipbc[tid] = sb;
        }
    }
}

// ---------------- half-slice kernel: block per ((b,t), feature-half) ----------------
__global__ __launch_bounds__(512) void k_slice2(const float* __restrict__ x,
                                                const float* __restrict__ cbg) {
    extern __shared__ float xs[];          // (Nc+1)*16, reused for edge features
    float* sipw = xs + (Nc + 1) * 16;      // 256: [k*16 + j]
    float* sipb = sipw + 256;              // 16
    int blk = blockIdx.x;
    int bt = blk >> 1;
    int half = blk & 1;
    int b = bt / Tc;
    int t = bt % Tc;
    int tid = threadIdx.x;
    int lane = tid & 31, w = tid >> 5;
    int fl = lane & 15;
    int sel = lane >> 4;
    int h16 = half * 16;

    if (tid < 256) {
        int k = tid >> 4, j = tid & 15;
        sipw[tid] = g_ipwc[k * 32 + h16 + j];
    }
    if (tid < 16) sipb[tid] = g_ipbc[h16 + tid];
    __syncthreads();

    const float* xb = x + (size_t)bt * Nc * F_INc;
    for (int i = tid; i < (Nc + 1) * 4; i += 512) {
        int n = i >> 2, q = (i & 3) * 4;
        float a0 = 0.f, a1 = 0.f, a2 = 0.f, a3 = 0.f;
        if (n < Nc) {
            const float* xr = xb + n * F_INc;
            a0 = sipb[q]; a1 = sipb[q + 1]; a2 = sipb[q + 2]; a3 = sipb[q + 3];
            #pragma unroll
            for (int k = 0; k < F_INc; k++) {
                float xv = xr[k];
                a0 += xv * sipw[k * 16 + q];
                a1 += xv * sipw[k * 16 + q + 1];
                a2 += xv * sipw[k * 16 + q + 2];
                a3 += xv * sipw[k * 16 + q + 3];
            }
            float d = g_dvi[b * Nc + n];
            a0 *= d; a1 *= d; a2 *= d; a3 *= d;
        }
        *(float4*)(xs + n * 16 + q) = make_float4(a0, a1, a2, a3);
    }
    __syncthreads();

    int e_base = w * 64;
    float u_reg[32];
    #pragma unroll
    for (int s = 0; s < 32; s++) {
        int e = e_base + 2 * s + sel;
        float uv = 0.f;
        if (e < Ec) {
            const int4* ip = (const int4*)(g_edge_nodes + e * ESTRIDE);
            int4 a0 = ip[0], a1 = ip[1], a2 = ip[2], a3 = ip[3], a4 = ip[4], a5 = ip[5];
            float p0 = xs[a0.x * 16 + fl] + xs[a1.x * 16 + fl]
                     + xs[a2.x * 16 + fl] + xs[a3.x * 16 + fl]
                     + xs[a4.x * 16 + fl] + xs[a5.x * 16 + fl];
            float p1 = xs[a0.y * 16 + fl] + xs[a1.y * 16 + fl]
                     + xs[a2.y * 16 + fl] + xs[a3.y * 16 + fl]
                     + xs[a4.y * 16 + fl] + xs[a5.y * 16 + fl];
            float p2 = xs[a0.z * 16 + fl] + xs[a1.z * 16 + fl]
                     + xs[a2.z * 16 + fl] + xs[a3.z * 16 + fl]
                     + xs[a4.z * 16 + fl] + xs[a5.z * 16 + fl];
            float p3 = xs[a0.w * 16 + fl] + xs[a1.w * 16 + fl]
                     + xs[a2.w * 16 + fl] + xs[a3.w * 16 + fl]
                     + xs[a4.w * 16 + fl] + xs[a5.w * 16 + fl];
            float sc = __fdividef(g_Wd[b * Ec + e], (float)g_edge_cnt[e]);
            uv = ((p0 + p1) + (p2 + p3)) * sc;
        }
        u_reg[s] = uv;
    }
    __syncthreads();

    #pragma unroll
    for (int s = 0; s < 32; s++) {
        int e = e_base + 2 * s + sel;
        if (e < Ec) xs[e * 16 + fl] = u_reg[s];
    }
    if (tid < 16) xs[Nc * 16 + tid] = 0.f;
    __syncthreads();

    float cbv = cbg[h16 + fl];
    for (int np = w; np < Nc / 2; np += 16) {
        int n = np * 2 + sel;
        int deg = g_node_deg[n];
        int d8 = (deg + 7) & ~7;
        const int* L = g_node_edges + n * MAXD;
        float p0 = 0.f, p1 = 0.f;
        for (int k = 0; k < d8; k += 8) {
            int4 a = *(const int4*)(L + k);
            int4 b2 = *(const int4*)(L + k + 4);
            p0 += xs[a.x * 16 + fl] + xs[a.z * 16 + fl]
                + xs[b2.x * 16 + fl] + xs[b2.z * 16 + fl];
            p1 += xs[a.y * 16 + fl] + xs[a.w * 16 + fl]
                + xs[b2.y * 16 + fl] + xs[b2.w * 16 + fl];
        }
        float z = (p0 + p1) * g_dvi[b * Nc + n] + cbv;
        g_hc[((size_t)(b * Nc + n) * Tc + t) * 32 + h16 + fl] = siluf(z);
    }
}

// ---------------- LSTM: tensor-core recurrence (tf32 2-pass split), 32 rows/block ----------------
// block = 32 rows, 4 warps. Warp g: gate-block cols [g*32,g*32+32), rows 0..31 (mt 0..1).
// Weights stationary in registers. State: warp w owns rows [w*8, w*8+8), lane = hidden index.
#define ASTR 68
#define ZSTR 132
__global__ __launch_bounds__(128) void k_lstm_tc(
    const float* __restrict__ wx, const float* __restrict__ wh,
    const float* __restrict__ lb,
    const float* __restrict__ hw1, const float* __restrict__ hb1,
    const float* __restrict__ hw2, const float* __restrict__ hb2,
    float* __restrict__ out, int Pout) {
    extern __shared__ __align__(16) float sm[];
    float* sAhi = sm;                    // 32*68 = 2176
    float* sAlo = sAhi + 32 * ASTR;      // 2176
    float* zbuf = sAlo + 32 * ASTR;      // 32*132 = 4224
    float* lbS  = zbuf + 32 * ZSTR;      // 128
    float* hw1S = lbS + 128;             // 1024
    float* hb1S = hw1S + 1024;           // 32
    float* hw2S = hb1S + 32;             // 384
    float* hb2S = hw2S + 384;            // 16

    int tid = threadIdx.x;
    int lane = tid & 31, w = tid >> 5;
    int gid = lane >> 2, tig = lane & 3;
    int gblk = w;
    int rb = blockIdx.x * 32;

    // stage head weights + biases
    for (int i = tid; i < 1024; i += 128) hw1S[i] = hw1[i];
    for (int i = tid; i < 384; i += 128) hw2S[i] = hw2[i];
    if (tid < 128) lbS[tid] = lb[tid];
    if (tid < 32) hb1S[tid] = hb1[tid];
    if (tid < PREDc) hb2S[tid] = hb2[tid];

    // stationary weights: B[k][n] = [wx;wh], warp's slice cols [gblk*32, +32)
    u32 bw0[8][4], bw1[8][4];
    #pragma unroll
    for (int ks = 0; ks < 8; ks++) {
        #pragma unroll
        for (int nt = 0; nt < 4; nt++) {
            int col = gblk * 32 + nt * 8 + gid;
            int k0 = ks * 8 + tig;
            int k1 = k0 + 4;
            float f0 = (k0 < 32) ? wx[k0 * 128 + col] : wh[(k0 - 32) * 128 + col];
            float f1 = (k1 < 32) ? wx[k1 * 128 + col] : wh[(k1 - 32) * 128 + col];
            bw0[ks][nt] = tf32_of(f0);
            bw1[ks][nt] = tf32_of(f1);
        }
    }

    // init state + fill sA for t=0 (warp owns rows [w*8, w*8+8), lane = hidden idx)
    int r0 = w * 8;
    float h[8], cst[8];
    #pragma unroll
    for (int q = 0; q < 8; q++) {
        h[q] = 0.f; cst[q] = 0.f;
        int r = r0 + q;
        float hc = g_hc[((size_t)(rb + r) * Tc) * 32 + lane];
        u32 hib = tf32_of(hc);
        float hif = __uint_as_float(hib);
        sAhi[r * ASTR + lane] = hif;
        sAlo[r * ASTR + lane] = hc - hif;
        sAhi[r * ASTR + 32 + lane] = 0.f;
        sAlo[r * ASTR + 32 + lane] = 0.f;
    }
    __syncthreads();

    for (int t = 0; t < Tc; t++) {
        // prefetch hc(t+1) for owned rows (hidden under mma phase)
        float hcn[8];
        if (t + 1 < Tc) {
            #pragma unroll
            for (int q = 0; q < 8; q++)
                hcn[q] = g_hc[((size_t)(rb + r0 + q) * Tc + t + 1) * 32 + lane];
        }

        // mma phase: z = [hc;h] @ W + lb  (2-pass hi/lo split), rows mt*16
        float cc[2][4][4];
        #pragma unroll
        for (int mt = 0; mt < 2; mt++) {
            #pragma unroll
            for (int nt = 0; nt < 4; nt++) {
                int col = gblk * 32 + nt * 8 + tig * 2;
                cc[mt][nt][0] = lbS[col];
                cc[mt][nt][1] = lbS[col + 1];
                cc[mt][nt][2] = lbS[col];
                cc[mt][nt][3] = lbS[col + 1];
            }
        }
        #pragma unroll
        for (int ks = 0; ks < 8; ks++) {
            #pragma unroll
            for (int mt = 0; mt < 2; mt++) {
                int row = mt * 16 + gid;
                int ca = ks * 8 + tig;
                u32 a0h = __float_as_uint(sAhi[row * ASTR + ca]);
                u32 a1h = __float_as_uint(sAhi[(row + 8) * ASTR + ca]);
                u32 a2h = __float_as_uint(sAhi[row * ASTR + ca + 4]);
                u32 a3h = __float_as_uint(sAhi[(row + 8) * ASTR + ca + 4]);
                u32 a0l = __float_as_uint(sAlo[row * ASTR + ca]);
                u32 a1l = __float_as_uint(sAlo[(row + 8) * ASTR + ca]);
                u32 a2l = __float_as_uint(sAlo[row * ASTR + ca + 4]);
                u32 a3l = __float_as_uint(sAlo[(row + 8) * ASTR + ca + 4]);
                #pragma unroll
                for (int nt = 0; nt < 4; nt++) {
                    mma_tf32(cc[mt][nt], a0h, a1h, a2h, a3h, bw0[ks][nt], bw1[ks][nt]);
                    mma_tf32(cc[mt][nt], a0l, a1l, a2l, a3l, bw0[ks][nt], bw1[ks][nt]);
                }
            }
        }
        // store z to zbuf
        #pragma unroll
        for (int mt = 0; mt < 2; mt++) {
            int row = mt * 16 + gid;
            #pragma unroll
            for (int nt = 0; nt < 4; nt++) {
                int col = gblk * 32 + nt * 8 + tig * 2;
                *(float2*)&zbuf[row * ZSTR + col] = make_float2(cc[mt][nt][0], cc[mt][nt][1]);
                *(float2*)&zbuf[(row + 8) * ZSTR + col] = make_float2(cc[mt][nt][2], cc[mt][nt][3]);
            }
        }
        __syncthreads();

        // state phase: owned rows
        #pragma unroll
        for (int q = 0; q < 8; q++) {
            int r = r0 + q;
            float zi = zbuf[r * ZSTR + lane];
            float zf = zbuf[r * ZSTR + 32 + lane];
            float zg = zbuf[r * ZSTR + 64 + lane];
            float zo = zbuf[r * ZSTR + 96 + lane];
            float ig = sigmf(zi);
            float fg = sigmf(zf);
            float gg = tanhf_(zg);
            float og = sigmf(zo);
            cst[q] = fg * cst[q] + ig * gg;
            h[q] = og * tanhf_(cst[q]);
            u32 hib = tf32_of(h[q]);
            float hif = __uint_as_float(hib);
            sAhi[r * ASTR + 32 + lane] = hif;
            sAlo[r * ASTR + 32 + lane] = h[q] - hif;
            if (t + 1 < Tc) {
                float hc = hcn[q];
                u32 cb2 = tf32_of(hc);
                float cf2 = __uint_as_float(cb2);
                sAhi[r * ASTR + lane] = cf2;
                sAlo[r * ASTR + lane] = hc - cf2;
            }
        }
        __syncthreads();
    }

    // head: y = silu(h @ hw1 + hb1) @ hw2 + hb2   (warp owns rows r0..r0+8)
    #pragma unroll
    for (int q = 0; q < 8; q++) {
        int row = rb + r0 + q;
        int b = row / Nc;
        int n = row % Nc;
        float a = hb1S[lane];
        #pragma unroll 8
        for (int i = 0; i < 32; i++) {
            float hi = __shfl_sync(FULLMASK, h[q], i);
            a += hi * hw1S[i * 32 + lane];
        }
        float y1 = siluf(a);
        float o = (lane < PREDc) ? hb2S[lane] : 0.f;
        #pragma unroll 8
        for (int j = 0; j < 32; j++) {
            float yj = __shfl_sync(FULLMASK, y1, j);
            if (lane < PREDc) o += yj * hw2S[j * PREDc + lane];
        }
        if (lane < Pout) out[((size_t)b * Pout + lane) * Nc + n] = o;
    }
}

// ---------------- launch ----------------
extern "C" void kernel_launch(void* const* d_in, const int* in_sizes, int n_in,
                              void* d_out, int out_size) {
    const float* x       = (const float*)d_in[0];
    const float* xraw    = (const float*)d_in[1];
    const float* W       = (const float*)d_in[3];
    const int*   members = (const int*)d_in[4];
    const int*   centers = (const int*)d_in[5];
    const int*   offsets = (const int*)d_in[6];
    const float* ipw     = (const float*)d_in[7];
    const float* ipb     = (const float*)d_in[8];
    const float* cw      = (const float*)d_in[9];
    const float* cb      = (const float*)d_in[10];
    const float* wx      = (const float*)d_in[11];
    const float* wh      = (const float*)d_in[12];
    const float* lb      = (const float*)d_in[13];
    const float* hw1     = (const float*)d_in[14];
    const float* hb1     = (const float*)d_in[15];
    const float* hw2     = (const float*)d_in[16];
    const float* hb2     = (const float*)d_in[17];
    float* out = (float*)d_out;
    int Pout = out_size / (Bc * Nc);

    int smem_slice = ((Nc + 1) * 16 + 256 + 16) * sizeof(float);                       // 65152
    int smem_lstm  = (32 * ASTR * 2 + 32 * ZSTR + 128 + 1024 + 32 + 384 + 16) * 4;     // ~41KB
    cudaFuncSetAttribute(k_slice2, cudaFuncAttributeMaxDynamicSharedMemorySize, smem_slice);
    cudaFuncSetAttribute(k_lstm_tc, cudaFuncAttributeMaxDynamicSharedMemorySize, smem_lstm);

    k_feat_zero<<<254, 256>>>(xraw);                       // feat + zero node degs
    k_sim_build<<<1004, 256>>>(members, centers, offsets); // sim + edge-list build
    k_sort_nodes<<<4, 256>>>();
    k_wdf<<<Bc + 1, 256>>>(W, ipw, ipb, cw);
    k_slice2<<<Bc * Tc * 2, 512, smem_slice>>>(x, cb);
    k_lstm_tc<<<Bc * Nc / 32, 128, smem_lstm>>>(wx, wh, lb, hw1, hb1, hw2, hb2, out, Pout);
}